// round 10
// baseline (speedup 1.0000x reference)
#include <cuda_runtime.h>
#include <math.h>

#define S_LEN 128
#define B_SZ  64
#define H_SZ  512
#define O_SZ  256
#define NMAX  8
#define NBLK  64

typedef unsigned long long u64;

// ---------------- device scratch (static; allocation is forbidden) ----------------
__device__ __align__(16) float g_preT[S_LEN * H_SZ * B_SZ];   // [t][j][b]
__device__ __align__(16) float g_accsT[S_LEN * H_SZ * B_SZ];  // [t][j][b]
__device__ __align__(16) float g_hbuf[3 * H_SZ * B_SZ];       // triple-buffer [buf][k][b]
__device__ __align__(16) float g_haltv[3 * NBLK * B_SZ];      // [buf][blk][b]
__device__ unsigned g_flag[NBLK * 32];                        // per-block flag, 128B stride

__device__ __forceinline__ void ffma2(u64 &d, u64 a, u64 b) {
    asm("fma.rn.f32x2 %0, %1, %2, %0;" : "+l"(d) : "l"(a), "l"(b));
}
__device__ __forceinline__ float lo32(u64 v) { return __uint_as_float((unsigned)(v & 0xffffffffu)); }
__device__ __forceinline__ float hi32(u64 v) { return __uint_as_float((unsigned)(v >> 32)); }
__device__ __forceinline__ u64 pack2(float x, float y) {
    return ((u64)__float_as_uint(y) << 32) | (u64)__float_as_uint(x);
}
__device__ __forceinline__ unsigned ld_acq(unsigned* p) {
    unsigned v;
    asm volatile("ld.acquire.gpu.u32 %0, [%1];" : "=r"(v) : "l"(p) : "memory");
    return v;
}
__device__ __forceinline__ void st_rel(unsigned* p, unsigned v) {
    asm volatile("st.release.gpu.u32 [%0], %1;" :: "l"(p), "r"(v) : "memory");
}

// ---------------- kernel 1: pre-projection GEMM ----------------
__global__ void __launch_bounds__(256) pre_gemm(const float* __restrict__ x,
                                                const float* __restrict__ W_ih,
                                                const float* __restrict__ b_ih,
                                                const float* __restrict__ b_hh) {
    __shared__ float Xs[64 * 65];
    __shared__ float Ws[64 * 65];
    const int t = blockIdx.y, jt = blockIdx.x;
    const int tid = threadIdx.x;
    const int ty = tid >> 4, tx = tid & 15;
    float acc[4][4] = {};
    for (int kc = 0; kc < 4; ++kc) {
        __syncthreads();
        for (int i = tid; i < 4096; i += 256) {
            int r = i >> 6, kk = i & 63;
            Xs[r * 65 + kk] = x[(t * 64 + r) * 256 + kc * 64 + kk];
            Ws[r * 65 + kk] = W_ih[(jt * 64 + r) * 257 + 1 + kc * 64 + kk];
        }
        __syncthreads();
        #pragma unroll 8
        for (int kk = 0; kk < 64; ++kk) {
            float wv[4], xv[4];
            #pragma unroll
            for (int a = 0; a < 4; ++a) wv[a] = Ws[(ty * 4 + a) * 65 + kk];
            #pragma unroll
            for (int c = 0; c < 4; ++c) xv[c] = Xs[(tx * 4 + c) * 65 + kk];
            #pragma unroll
            for (int a = 0; a < 4; ++a)
                #pragma unroll
                for (int c = 0; c < 4; ++c)
                    acc[a][c] = fmaf(wv[a], xv[c], acc[a][c]);
        }
    }
    #pragma unroll
    for (int a = 0; a < 4; ++a) {
        int j = jt * 64 + ty * 4 + a;
        float bias = b_ih[j] + b_hh[j];
        #pragma unroll
        for (int c = 0; c < 4; ++c) {
            int b = tx * 4 + c;
            g_preT[(t * 512 + j) * 64 + b] = acc[a][c] + bias;
        }
    }
}

// ---------------- init: s -> buf0 [k][b]; reset flags (self-heal every launch) ----------------
__global__ void init_h(const float* __restrict__ s) {
    if (threadIdx.x == 0) g_flag[blockIdx.x * 32] = 0u;
    int b = blockIdx.x;
    int j = threadIdx.x;
    g_hbuf[j * 64 + b] = s[b * 512 + j];
}

// ---------------- kernel 2: persistent ACT recurrence (dataflow-flag pipeline) ----------------
__global__ void __launch_bounds__(256, 1) rnn_act(const float* __restrict__ W_hh,
                                                  const float* __restrict__ W_ih,
                                                  const float* __restrict__ W_halt,
                                                  const float* __restrict__ b_halt,
                                                  float* __restrict__ pond_out) {
    __shared__ __align__(16) u64   sh_W2[4096];    // [k=512][j=8] dup-pairs (32 KB)
    __shared__ __align__(16) u64   sh_part[1024];  // [grp=4][j=8][lane=32]    (8 KB)
    __shared__ float sh_hp[512];                   // halt partials [warp=8][b=64]
    __shared__ float sh_hn[512];                   // current h slice [j=8][b=64]
    __shared__ float sh_cum[64];
    __shared__ float sh_w[64];
    __shared__ float sh_pond[64];
    __shared__ int   sh_halted[64];
    __shared__ float sh_whalt[8];
    __shared__ float sh_wih0[8];
    __shared__ float sh_bhalt;

    const int blk  = blockIdx.x;
    const int tid  = threadIdx.x;
    const int warp = tid >> 5, lane = tid & 31;
    const int j = warp, b0 = lane * 2;             // thread <-> (j, b-pair) mapping
    const int gj = blk * 8 + j;

    // one-time: W_hh slice -> SMEM as duplicated f32x2 pairs, layout [k][j]
    for (int i = tid; i < 4096; i += 256) {
        int jj = i >> 9, k = i & 511;
        unsigned wb = __float_as_uint(W_hh[(blk * 8 + jj) * 512 + k]);
        sh_W2[k * 8 + jj] = ((u64)wb << 32) | (u64)wb;
    }
    if (tid < 8) {
        sh_whalt[tid] = W_halt[blk * 8 + tid];
        sh_wih0[tid]  = W_ih[(blk * 8 + tid) * 257];
    }
    if (tid == 0) sh_bhalt = b_halt[0];
    if (tid < 64) { sh_cum[tid] = 0.f; sh_pond[tid] = 0.f; sh_halted[tid] = 0; }
    __syncthreads();

    unsigned m = 0;               // global step counter (monotonic)
    int m3 = 0, nx3 = 1;          // m % 3, (m+1) % 3
    int t = 0, n = 0;             // timestep, local ponder index (uniform across blocks)
    float accx = 0.f, accy = 0.f; // acc_s for (j, b0/b0+1)
    float hpx = 0.f, hpy = 0.f;   // previous-step h for (j, b0/b0+1)

    const int fidx = (warp << 3) + (lane < 8 ? lane : 0);
    unsigned* myflag = &g_flag[fidx << 5];

    while (t < S_LEN) {
        // ---- prefetch this step's pre-projection BEFORE the wait ----
        const float2 pre2 = __ldg((const float2*)(g_preT + ((t * 512 + gj) << 6) + b0));
        // ---- phase 1: tight-spin readiness check (8 producers per warp) ----
        {
            int polls = 0;
            for (;;) {
                unsigned v = (lane < 8) ? ld_acq(myflag) : 0xffffffffu;
                if (__all_sync(0xffffffffu, v >= m)) break;
                if (++polls > 4096) { __nanosleep(64); polls = 0; }
            }
        }
        // ---- consume chunks + GEMM + halt-partial accumulate ----
        u64 q0=0,q1=0,q2=0,q3=0,q4=0,q5=0,q6=0,q7=0;
        float hpa = 0.f, hpb = 0.f;
        {
            const u64*   bufr = (const u64*)g_hbuf + m3 * 16384;
            const float* hvr  = g_haltv + m3 * 4096;
            #pragma unroll
            for (int c8 = 0; c8 < 8; ++c8) {
                const int pb = (warp << 3) + c8;
                const u64* rp = bufr + (pb << 8) + lane;
                #pragma unroll
                for (int kk = 0; kk < 8; ++kk) {
                    u64 h2 = __ldcg(rp + (kk << 5));
                    const ulonglong2* wr = (const ulonglong2*)(sh_W2 + (((pb << 3) + kk) << 3));
                    ulonglong2 w01 = wr[0], w23 = wr[1], w45 = wr[2], w67 = wr[3];
                    ffma2(q0, h2, w01.x); ffma2(q1, h2, w01.y);
                    ffma2(q2, h2, w23.x); ffma2(q3, h2, w23.y);
                    ffma2(q4, h2, w45.x); ffma2(q5, h2, w45.y);
                    ffma2(q6, h2, w67.x); ffma2(q7, h2, w67.y);
                }
                hpa += __ldcg(hvr + (pb << 6) + lane);
                hpb += __ldcg(hvr + (pb << 6) + 32 + lane);
            }
        }
        // ---- phase 2: stage K-partials (warps 0-3) + halt partials (all warps) ----
        if (warp < 4) {
            u64* pp = sh_part + (warp << 8) + lane;
            pp[0*32]=q0; pp[1*32]=q1; pp[2*32]=q2; pp[3*32]=q3;
            pp[4*32]=q4; pp[5*32]=q5; pp[6*32]=q6; pp[7*32]=q7;
        }
        sh_hp[(warp << 6) + lane]      = hpa;
        sh_hp[(warp << 6) + 32 + lane] = hpb;
        __syncthreads();
        // ---- phase 3: warps 4-7 fold; threads 0-63 finalize halting for q = n-1 ----
        if (warp >= 4) {
            u64* pp = sh_part + ((warp - 4) << 8) + lane;
            u64 v;
            v = pp[0*32]; pp[0*32] = pack2(lo32(v)+lo32(q0), hi32(v)+hi32(q0));
            v = pp[1*32]; pp[1*32] = pack2(lo32(v)+lo32(q1), hi32(v)+hi32(q1));
            v = pp[2*32]; pp[2*32] = pack2(lo32(v)+lo32(q2), hi32(v)+hi32(q2));
            v = pp[3*32]; pp[3*32] = pack2(lo32(v)+lo32(q3), hi32(v)+hi32(q3));
            v = pp[4*32]; pp[4*32] = pack2(lo32(v)+lo32(q4), hi32(v)+hi32(q4));
            v = pp[5*32]; pp[5*32] = pack2(lo32(v)+lo32(q5), hi32(v)+hi32(q5));
            v = pp[6*32]; pp[6*32] = pack2(lo32(v)+lo32(q6), hi32(v)+hi32(q6));
            v = pp[7*32]; pp[7*32] = pack2(lo32(v)+lo32(q7), hi32(v)+hi32(q7));
        }
        if (n >= 1 && tid < 64) {
            float s = 0.f;
            #pragma unroll
            for (int w8 = 0; w8 < 8; ++w8) s += sh_hp[(w8 << 6) + tid];   // fixed order
            float p = 1.f / (1.f + expf(-(s + sh_bhalt)));
            int hl = sh_halted[tid];
            if (hl) p = 0.f;
            float cum = sh_cum[tid];
            int is_h = (!hl) && (((cum + p) >= 0.99f) || (n - 1 == NMAX - 1));
            sh_w[tid] = is_h ? (1.f - cum) : p;
            if (is_h) sh_pond[tid] = (1.f - cum) + (float)n;   // (q+1) = n
            sh_cum[tid] = cum + p;
            sh_halted[tid] = hl | is_h;
        }
        int allh = __syncthreads_and((n == 0) ? 0 : (tid < 64 ? sh_halted[tid] : 1));
        // ---- phase 4: acc update (lagged), then write h_new or carry ----
        {
            if (n >= 1) { accx += sh_w[b0] * hpx; accy += sh_w[b0 + 1] * hpy; }
            u64* bw = (u64*)g_hbuf + nx3 * 16384 + (gj << 5) + lane;
            if (!allh) {
                float sx = 0.f, sy = 0.f;
                #pragma unroll
                for (int g = 0; g < 4; ++g) {
                    u64 v = sh_part[((g << 3) + j) * 32 + lane];
                    sx += lo32(v); sy += hi32(v);
                }
                float ax = sx + pre2.x, ay = sy + pre2.y;
                if (n == 0) { float f = sh_wih0[j]; ax += f; ay += f; }
                float hx = tanhf(ax), hyv = tanhf(ay);
                hpx = hx; hpy = hyv;
                sh_hn[(j << 6) + b0]     = hx;
                sh_hn[(j << 6) + b0 + 1] = hyv;
                *bw = pack2(hx, hyv);
            } else {
                *bw = pack2(accx, accy);   // carry = acc_s -> next timestep's h input
            }
        }
        __syncthreads();
        // ---- tail: warp 7 publishes haltv + releases; others do housekeeping ----
        if (warp == 7) {
            if (!allh) {
                // haltv[b] = sum_j whalt[j] * h_new[j][b] for this block (fixed j order)
                float s0 = 0.f, s1 = 0.f;
                #pragma unroll
                for (int jj = 0; jj < 8; ++jj) {
                    s0 += sh_whalt[jj] * sh_hn[(jj << 6) + b0];
                    s1 += sh_whalt[jj] * sh_hn[(jj << 6) + b0 + 1];
                }
                *(float2*)(g_haltv + nx3 * 4096 + (blk << 6) + b0) = make_float2(s0, s1);
            }
            __syncwarp();
            if (lane == 0) {
                __threadfence();              // make h (+haltv) visible gpu-wide
                st_rel(&g_flag[blk << 5], m + 1);
            }
        }
        if (!allh) {
            ++n;
        } else {
            *(float2*)(g_accsT + ((t * 512 + gj) << 6) + b0) = make_float2(accx, accy);
            if (blk == 0 && tid < 64) pond_out[t * 64 + tid] = sh_pond[tid];
            if (tid < 64) { sh_cum[tid] = 0.f; sh_pond[tid] = 0.f; sh_halted[tid] = 0; }
            accx = accy = 0.f;
            ++t; n = 0;
        }
        ++m;
        m3 = nx3; nx3 = (nx3 + 1 == 3) ? 0 : nx3 + 1;
    }
}

// ---------------- kernel 3: output GEMM ----------------
__global__ void __launch_bounds__(256) out_gemm(const float* __restrict__ W_out,
                                                const float* __restrict__ b_out,
                                                float* __restrict__ out) {
    __shared__ float As[64 * 65];
    __shared__ float Ws[64 * 65];
    const int t = blockIdx.y, ot = blockIdx.x;
    const int tid = threadIdx.x;
    const int ty = tid >> 4, tx = tid & 15;
    float acc[4][4] = {};
    for (int kc = 0; kc < 8; ++kc) {
        __syncthreads();
        for (int i = tid; i < 4096; i += 256) {
            int r = i >> 6, c = i & 63;
            As[r * 65 + c] = g_accsT[(t * 512 + kc * 64 + r) * 64 + c];
            Ws[r * 65 + c] = W_out[(ot * 64 + r) * 512 + kc * 64 + c];
        }
        __syncthreads();
        #pragma unroll 8
        for (int kk = 0; kk < 64; ++kk) {
            float wv[4], xv[4];
            #pragma unroll
            for (int a = 0; a < 4; ++a) wv[a] = Ws[(ty * 4 + a) * 65 + kk];
            #pragma unroll
            for (int c = 0; c < 4; ++c) xv[c] = As[kk * 65 + tx * 4 + c];
            #pragma unroll
            for (int a = 0; a < 4; ++a)
                #pragma unroll
                for (int c = 0; c < 4; ++c)
                    acc[a][c] = fmaf(wv[a], xv[c], acc[a][c]);
        }
    }
    #pragma unroll
    for (int a = 0; a < 4; ++a) {
        int o = ot * 64 + ty * 4 + a;
        float bias = b_out[o];
        #pragma unroll
        for (int c = 0; c < 4; ++c) {
            int b = tx * 4 + c;
            out[(t * 64 + b) * 256 + o] = acc[a][c] + bias;
        }
    }
}

extern "C" void kernel_launch(void* const* d_in, const int* in_sizes, int n_in,
                              void* d_out, int out_size) {
    const float* x      = (const float*)d_in[0];
    const float* s      = (const float*)d_in[1];
    const float* W_ih   = (const float*)d_in[2];
    const float* b_ih   = (const float*)d_in[3];
    const float* W_hh   = (const float*)d_in[4];
    const float* b_hh   = (const float*)d_in[5];
    const float* W_out  = (const float*)d_in[6];
    const float* b_out  = (const float*)d_in[7];
    const float* W_halt = (const float*)d_in[8];
    const float* b_halt = (const float*)d_in[9];
    float* out  = (float*)d_out;                       // outputs [S,B,O]
    float* pond = out + S_LEN * B_SZ * O_SZ;           // ponder  [S,B]

    dim3 preg(8, S_LEN);
    pre_gemm<<<preg, 256>>>(x, W_ih, b_ih, b_hh);
    init_h<<<B_SZ, H_SZ>>>(s);
    rnn_act<<<NBLK, 256>>>(W_hh, W_ih, W_halt, b_halt, pond);
    dim3 outg(4, S_LEN);
    out_gemm<<<outg, 256>>>(W_out, b_out, out);
}

// round 11
// speedup vs baseline: 1.3426x; 1.3426x over previous
#include <cuda_runtime.h>
#include <math.h>

#define S_LEN 128
#define B_SZ  64
#define H_SZ  512
#define O_SZ  256
#define NMAX  8
#define NBLK  128   // persistent blocks, 4 neurons each (128 <= 148 SMs)

typedef unsigned long long u64;

// ---------------- device scratch (static; allocation is forbidden) ----------------
__device__ __align__(16) float g_preT[S_LEN * H_SZ * B_SZ];   // [t][j][b]
__device__ __align__(16) float g_accsT[S_LEN * H_SZ * B_SZ];  // [t][j][b]
__device__ __align__(16) float g_hbuf[3 * H_SZ * B_SZ];       // triple-buffer [buf][k][b]
__device__ __align__(16) float g_haltv[3 * NBLK * B_SZ];      // [buf][blk][b]
__device__ unsigned g_flag[NBLK * 32];                        // per-block flag, 128B stride

__device__ __forceinline__ void ffma2(u64 &d, u64 a, u64 b) {
    asm("fma.rn.f32x2 %0, %1, %2, %0;" : "+l"(d) : "l"(a), "l"(b));
}
__device__ __forceinline__ float lo32(u64 v) { return __uint_as_float((unsigned)(v & 0xffffffffu)); }
__device__ __forceinline__ float hi32(u64 v) { return __uint_as_float((unsigned)(v >> 32)); }
__device__ __forceinline__ u64 pack2(float x, float y) {
    return ((u64)__float_as_uint(y) << 32) | (u64)__float_as_uint(x);
}
__device__ __forceinline__ unsigned ld_acq(unsigned* p) {
    unsigned v;
    asm volatile("ld.acquire.gpu.u32 %0, [%1];" : "=r"(v) : "l"(p) : "memory");
    return v;
}
__device__ __forceinline__ void st_rel(unsigned* p, unsigned v) {
    asm volatile("st.release.gpu.u32 [%0], %1;" :: "l"(p), "r"(v) : "memory");
}

// ---------------- kernel 1: pre-projection GEMM ----------------
__global__ void __launch_bounds__(256) pre_gemm(const float* __restrict__ x,
                                                const float* __restrict__ W_ih,
                                                const float* __restrict__ b_ih,
                                                const float* __restrict__ b_hh) {
    __shared__ float Xs[64 * 65];
    __shared__ float Ws[64 * 65];
    const int t = blockIdx.y, jt = blockIdx.x;
    const int tid = threadIdx.x;
    const int ty = tid >> 4, tx = tid & 15;
    float acc[4][4] = {};
    for (int kc = 0; kc < 4; ++kc) {
        __syncthreads();
        for (int i = tid; i < 4096; i += 256) {
            int r = i >> 6, kk = i & 63;
            Xs[r * 65 + kk] = x[(t * 64 + r) * 256 + kc * 64 + kk];
            Ws[r * 65 + kk] = W_ih[(jt * 64 + r) * 257 + 1 + kc * 64 + kk];
        }
        __syncthreads();
        #pragma unroll 8
        for (int kk = 0; kk < 64; ++kk) {
            float wv[4], xv[4];
            #pragma unroll
            for (int a = 0; a < 4; ++a) wv[a] = Ws[(ty * 4 + a) * 65 + kk];
            #pragma unroll
            for (int c = 0; c < 4; ++c) xv[c] = Xs[(tx * 4 + c) * 65 + kk];
            #pragma unroll
            for (int a = 0; a < 4; ++a)
                #pragma unroll
                for (int c = 0; c < 4; ++c)
                    acc[a][c] = fmaf(wv[a], xv[c], acc[a][c]);
        }
    }
    #pragma unroll
    for (int a = 0; a < 4; ++a) {
        int j = jt * 64 + ty * 4 + a;
        float bias = b_ih[j] + b_hh[j];
        #pragma unroll
        for (int c = 0; c < 4; ++c) {
            int b = tx * 4 + c;
            g_preT[(t * 512 + j) * 64 + b] = acc[a][c] + bias;
        }
    }
}

// ---------------- init: s -> buf0 [k][b]; reset all 128 flags ----------------
__global__ void init_h(const float* __restrict__ s) {
    if (threadIdx.x < 2) g_flag[(blockIdx.x * 2 + threadIdx.x) * 32] = 0u;
    int b = blockIdx.x;
    int j = threadIdx.x;
    g_hbuf[j * 64 + b] = s[b * 512 + j];
}

// ---------------- kernel 2: persistent ACT recurrence (128 blocks x 4 neurons) ----------------
__global__ void __launch_bounds__(256, 1) rnn_act(const float* __restrict__ W_hh,
                                                  const float* __restrict__ W_ih,
                                                  const float* __restrict__ W_halt,
                                                  const float* __restrict__ b_halt,
                                                  float* __restrict__ pond_out) {
    __shared__ __align__(16) u64   sh_W2[2048];    // [k=512][j=4] dup-pairs (16 KB)
    __shared__ __align__(16) u64   sh_part[512];   // [grp=4][j=4][lane=32]    (4 KB)
    __shared__ float sh_hp[512];                   // halt partials [warp=8][b=64]
    __shared__ float sh_hn[256];                   // current h slice [j=4][b=64]
    __shared__ float sh_cum[64];
    __shared__ float sh_w[64];
    __shared__ float sh_pond[64];
    __shared__ int   sh_halted[64];
    __shared__ float sh_whalt[4];
    __shared__ float sh_wih0[4];
    __shared__ float sh_bhalt;

    const int blk  = blockIdx.x;
    const int tid  = threadIdx.x;
    const int warp = tid >> 5, lane = tid & 31;
    const int jo = warp & 3, b0 = lane * 2;        // output mapping (warps 4-7 shadow 0-3)
    const int gj = blk * 4 + jo;

    // one-time: W_hh slice (4 rows) -> SMEM dup-pairs, layout [k][j]
    for (int i = tid; i < 2048; i += 256) {
        int jj = i >> 9, k = i & 511;
        unsigned wb = __float_as_uint(W_hh[(blk * 4 + jj) * 512 + k]);
        sh_W2[k * 4 + jj] = ((u64)wb << 32) | (u64)wb;
    }
    if (tid < 4) {
        sh_whalt[tid] = W_halt[blk * 4 + tid];
        sh_wih0[tid]  = W_ih[(blk * 4 + tid) * 257];
    }
    if (tid == 0) sh_bhalt = b_halt[0];
    if (tid < 64) { sh_cum[tid] = 0.f; sh_pond[tid] = 0.f; sh_halted[tid] = 0; }
    __syncthreads();

    unsigned m = 0;               // global step counter (monotonic)
    int m3 = 0, nx3 = 1;          // m % 3, (m+1) % 3
    int t = 0, n = 0;             // timestep, local ponder index (uniform across blocks)
    float accx = 0.f, accy = 0.f; // acc_s for (jo, b0/b0+1)
    float hpx = 0.f, hpy = 0.f;   // previous-step h for (jo, b0/b0+1)

    unsigned* myflag = &g_flag[(((warp << 4) + (lane < 16 ? lane : 0)) << 5)];

    while (t < S_LEN) {
        // ---- prefetch this step's pre-projection BEFORE the wait ----
        const float2 pre2 = __ldg((const float2*)(g_preT + ((t * 512 + gj) << 6) + b0));
        // ---- phase 1: readiness check for this warp's 16 producers ----
        for (;;) {
            unsigned v = (lane < 16) ? ld_acq(myflag) : 0xffffffffu;
            if (__all_sync(0xffffffffu, v >= m)) break;
            __nanosleep(32);
        }
        // ---- GEMM (K-slice 64 per warp, 4 j) + halt-partial accumulate ----
        u64 a0 = 0, a1 = 0, a2 = 0, a3 = 0;
        float hpa = 0.f, hpb = 0.f;
        {
            const u64*   bufr = (const u64*)g_hbuf + m3 * 16384;
            const float* hvr  = g_haltv + m3 * 8192;
            #pragma unroll
            for (int pc = 0; pc < 16; ++pc) {
                const int k0 = (warp << 6) + (pc << 2);
                #pragma unroll
                for (int kk = 0; kk < 4; ++kk) {
                    u64 h2 = __ldcg(bufr + ((k0 + kk) << 5) + lane);
                    const ulonglong2* wr = (const ulonglong2*)(sh_W2 + ((k0 + kk) << 2));
                    ulonglong2 w01 = wr[0], w23 = wr[1];
                    ffma2(a0, h2, w01.x); ffma2(a1, h2, w01.y);
                    ffma2(a2, h2, w23.x); ffma2(a3, h2, w23.y);
                }
                const int pb = (warp << 4) + pc;
                hpa += __ldcg(hvr + (pb << 6) + lane);
                hpb += __ldcg(hvr + (pb << 6) + 32 + lane);
            }
        }
        // ---- stage K-partials (warps 0-3) + halt partials (all warps) ----
        if (warp < 4) {
            u64* pp = sh_part + (warp << 7) + lane;
            pp[0*32]=a0; pp[1*32]=a1; pp[2*32]=a2; pp[3*32]=a3;
        }
        sh_hp[(warp << 6) + lane]      = hpa;
        sh_hp[(warp << 6) + 32 + lane] = hpb;
        __syncthreads();
        // ---- warps 4-7 fold; threads 0-63 finalize halting for q = n-1 ----
        if (warp >= 4) {
            u64* pp = sh_part + ((warp - 4) << 7) + lane;
            u64 v;
            v = pp[0*32]; pp[0*32] = pack2(lo32(v)+lo32(a0), hi32(v)+hi32(a0));
            v = pp[1*32]; pp[1*32] = pack2(lo32(v)+lo32(a1), hi32(v)+hi32(a1));
            v = pp[2*32]; pp[2*32] = pack2(lo32(v)+lo32(a2), hi32(v)+hi32(a2));
            v = pp[3*32]; pp[3*32] = pack2(lo32(v)+lo32(a3), hi32(v)+hi32(a3));
        }
        if (n >= 1 && tid < 64) {
            float s = 0.f;
            #pragma unroll
            for (int w8 = 0; w8 < 8; ++w8) s += sh_hp[(w8 << 6) + tid];   // fixed order
            float p = 1.f / (1.f + expf(-(s + sh_bhalt)));
            int hl = sh_halted[tid];
            if (hl) p = 0.f;
            float cum = sh_cum[tid];
            int is_h = (!hl) && (((cum + p) >= 0.99f) || (n - 1 == NMAX - 1));
            sh_w[tid] = is_h ? (1.f - cum) : p;
            if (is_h) sh_pond[tid] = (1.f - cum) + (float)n;   // (q+1) = n
            sh_cum[tid] = cum + p;
            sh_halted[tid] = hl | is_h;
        }
        int allh = __syncthreads_and((n == 0) ? 0 : (tid < 64 ? sh_halted[tid] : 1));
        // ---- acc update (lagged), then write h_new or carry (stores gated warp<4) ----
        {
            if (n >= 1) { accx += sh_w[b0] * hpx; accy += sh_w[b0 + 1] * hpy; }
            u64* bw = (u64*)g_hbuf + nx3 * 16384 + (gj << 5) + lane;
            if (!allh) {
                float sx = 0.f, sy = 0.f;
                #pragma unroll
                for (int g = 0; g < 4; ++g) {
                    u64 v = sh_part[(g << 7) + (jo << 5) + lane];
                    sx += lo32(v); sy += hi32(v);
                }
                float ax = sx + pre2.x, ay = sy + pre2.y;
                if (n == 0) { float f = sh_wih0[jo]; ax += f; ay += f; }
                float hx = tanhf(ax), hyv = tanhf(ay);
                hpx = hx; hpy = hyv;
                if (warp < 4) {
                    sh_hn[(jo << 6) + b0]     = hx;
                    sh_hn[(jo << 6) + b0 + 1] = hyv;
                    *bw = pack2(hx, hyv);
                }
            } else {
                if (warp < 4) *bw = pack2(accx, accy);   // carry = acc_s
            }
        }
        __syncthreads();
        // ---- publish halt vector (or finish timestep) ----
        if (!allh) {
            if (tid < 64) {
                float s = 0.f;
                #pragma unroll
                for (int jj = 0; jj < 4; ++jj) s += sh_whalt[jj] * sh_hn[(jj << 6) + tid];
                g_haltv[nx3 * 8192 + (blk << 6) + tid] = s;
            }
            ++n;
        } else {
            if (warp < 4)
                *(float2*)(g_accsT + ((t * 512 + gj) << 6) + b0) = make_float2(accx, accy);
            if (blk == 0 && tid < 64) pond_out[t * 64 + tid] = sh_pond[tid];
            if (tid < 64) { sh_cum[tid] = 0.f; sh_pond[tid] = 0.f; sh_halted[tid] = 0; }
            accx = accy = 0.f;
            ++t; n = 0;
        }
        __syncthreads();
        // ---- release this block's flag for step m+1 ----
        if (tid == 0) st_rel(&g_flag[blk << 5], m + 1);
        ++m;
        m3 = nx3; nx3 = (nx3 + 1 == 3) ? 0 : nx3 + 1;
    }
}

// ---------------- kernel 3: output GEMM ----------------
__global__ void __launch_bounds__(256) out_gemm(const float* __restrict__ W_out,
                                                const float* __restrict__ b_out,
                                                float* __restrict__ out) {
    __shared__ float As[64 * 65];
    __shared__ float Ws[64 * 65];
    const int t = blockIdx.y, ot = blockIdx.x;
    const int tid = threadIdx.x;
    const int ty = tid >> 4, tx = tid & 15;
    float acc[4][4] = {};
    for (int kc = 0; kc < 8; ++kc) {
        __syncthreads();
        for (int i = tid; i < 4096; i += 256) {
            int r = i >> 6, c = i & 63;
            As[r * 65 + c] = g_accsT[(t * 512 + kc * 64 + r) * 64 + c];
            Ws[r * 65 + c] = W_out[(ot * 64 + r) * 512 + kc * 64 + c];
        }
        __syncthreads();
        #pragma unroll 8
        for (int kk = 0; kk < 64; ++kk) {
            float wv[4], xv[4];
            #pragma unroll
            for (int a = 0; a < 4; ++a) wv[a] = Ws[(ty * 4 + a) * 65 + kk];
            #pragma unroll
            for (int c = 0; c < 4; ++c) xv[c] = As[kk * 65 + tx * 4 + c];
            #pragma unroll
            for (int a = 0; a < 4; ++a)
                #pragma unroll
                for (int c = 0; c < 4; ++c)
                    acc[a][c] = fmaf(wv[a], xv[c], acc[a][c]);
        }
    }
    #pragma unroll
    for (int a = 0; a < 4; ++a) {
        int o = ot * 64 + ty * 4 + a;
        float bias = b_out[o];
        #pragma unroll
        for (int c = 0; c < 4; ++c) {
            int b = tx * 4 + c;
            out[(t * 64 + b) * 256 + o] = acc[a][c] + bias;
        }
    }
}

extern "C" void kernel_launch(void* const* d_in, const int* in_sizes, int n_in,
                              void* d_out, int out_size) {
    const float* x      = (const float*)d_in[0];
    const float* s      = (const float*)d_in[1];
    const float* W_ih   = (const float*)d_in[2];
    const float* b_ih   = (const float*)d_in[3];
    const float* W_hh   = (const float*)d_in[4];
    const float* b_hh   = (const float*)d_in[5];
    const float* W_out  = (const float*)d_in[6];
    const float* b_out  = (const float*)d_in[7];
    const float* W_halt = (const float*)d_in[8];
    const float* b_halt = (const float*)d_in[9];
    float* out  = (float*)d_out;                       // outputs [S,B,O]
    float* pond = out + S_LEN * B_SZ * O_SZ;           // ponder  [S,B]

    dim3 preg(8, S_LEN);
    pre_gemm<<<preg, 256>>>(x, W_ih, b_ih, b_hh);
    init_h<<<B_SZ, H_SZ>>>(s);
    rnn_act<<<NBLK, 256>>>(W_hh, W_ih, W_halt, b_halt, pond);
    dim3 outg(4, S_LEN);
    out_gemm<<<outg, 256>>>(W_out, b_out, out);
}

// round 12
// speedup vs baseline: 1.3766x; 1.0253x over previous
#include <cuda_runtime.h>
#include <math.h>

#define S_LEN 128
#define B_SZ  64
#define H_SZ  512
#define O_SZ  256
#define NMAX  8
#define NBLK  128   // persistent blocks, 4 neurons each (128 <= 148 SMs)

typedef unsigned long long u64;

// ---------------- device scratch (static; allocation is forbidden) ----------------
__device__ __align__(16) float g_preT[S_LEN * H_SZ * B_SZ];   // [t][j][b]
__device__ __align__(16) float g_accsT[S_LEN * H_SZ * B_SZ];  // [t][j][b]
__device__ __align__(16) float g_hbuf[3 * H_SZ * B_SZ];       // triple-buffer [buf][k][b]
__device__ __align__(16) float g_haltv[3 * NBLK * B_SZ];      // [buf][blk][b]
__device__ unsigned g_flag[NBLK * 32];                        // per-block flag, 128B stride

__device__ __forceinline__ void ffma2(u64 &d, u64 a, u64 b) {
    asm("fma.rn.f32x2 %0, %1, %2, %0;" : "+l"(d) : "l"(a), "l"(b));
}
__device__ __forceinline__ u64 add2(u64 a, u64 b) {
    u64 r;
    asm("add.rn.f32x2 %0, %1, %2;" : "=l"(r) : "l"(a), "l"(b));
    return r;
}
__device__ __forceinline__ float lo32(u64 v) { return __uint_as_float((unsigned)(v & 0xffffffffu)); }
__device__ __forceinline__ float hi32(u64 v) { return __uint_as_float((unsigned)(v >> 32)); }
__device__ __forceinline__ u64 pack2(float x, float y) {
    return ((u64)__float_as_uint(y) << 32) | (u64)__float_as_uint(x);
}
__device__ __forceinline__ unsigned ld_acq(unsigned* p) {
    unsigned v;
    asm volatile("ld.acquire.gpu.u32 %0, [%1];" : "=r"(v) : "l"(p) : "memory");
    return v;
}
__device__ __forceinline__ void st_rel(unsigned* p, unsigned v) {
    asm volatile("st.release.gpu.u32 [%0], %1;" :: "l"(p), "r"(v) : "memory");
}

// ---------------- kernel 1: pre-projection GEMM ----------------
__global__ void __launch_bounds__(256) pre_gemm(const float* __restrict__ x,
                                                const float* __restrict__ W_ih,
                                                const float* __restrict__ b_ih,
                                                const float* __restrict__ b_hh) {
    __shared__ float Xs[64 * 65];
    __shared__ float Ws[64 * 65];
    const int t = blockIdx.y, jt = blockIdx.x;
    const int tid = threadIdx.x;
    const int ty = tid >> 4, tx = tid & 15;
    float acc[4][4] = {};
    for (int kc = 0; kc < 4; ++kc) {
        __syncthreads();
        for (int i = tid; i < 4096; i += 256) {
            int r = i >> 6, kk = i & 63;
            Xs[r * 65 + kk] = x[(t * 64 + r) * 256 + kc * 64 + kk];
            Ws[r * 65 + kk] = W_ih[(jt * 64 + r) * 257 + 1 + kc * 64 + kk];
        }
        __syncthreads();
        #pragma unroll 8
        for (int kk = 0; kk < 64; ++kk) {
            float wv[4], xv[4];
            #pragma unroll
            for (int a = 0; a < 4; ++a) wv[a] = Ws[(ty * 4 + a) * 65 + kk];
            #pragma unroll
            for (int c = 0; c < 4; ++c) xv[c] = Xs[(tx * 4 + c) * 65 + kk];
            #pragma unroll
            for (int a = 0; a < 4; ++a)
                #pragma unroll
                for (int c = 0; c < 4; ++c)
                    acc[a][c] = fmaf(wv[a], xv[c], acc[a][c]);
        }
    }
    #pragma unroll
    for (int a = 0; a < 4; ++a) {
        int j = jt * 64 + ty * 4 + a;
        float bias = b_ih[j] + b_hh[j];
        #pragma unroll
        for (int c = 0; c < 4; ++c) {
            int b = tx * 4 + c;
            g_preT[(t * 512 + j) * 64 + b] = acc[a][c] + bias;
        }
    }
}

// ---------------- init: s -> buf0 [k][b]; reset all 128 flags ----------------
__global__ void init_h(const float* __restrict__ s) {
    if (threadIdx.x < 2) g_flag[(blockIdx.x * 2 + threadIdx.x) * 32] = 0u;
    int b = blockIdx.x;
    int j = threadIdx.x;
    g_hbuf[j * 64 + b] = s[b * 512 + j];
}

// ---------------- kernel 2: persistent ACT recurrence (128 blocks x 4 neurons) ----------------
__global__ void __launch_bounds__(256, 1) rnn_act(const float* __restrict__ W_hh,
                                                  const float* __restrict__ W_ih,
                                                  const float* __restrict__ W_halt,
                                                  const float* __restrict__ b_halt,
                                                  float* __restrict__ pond_out) {
    __shared__ __align__(16) u64   sh_W2[2048];    // [k=512][j=4] dup-pairs (16 KB)
    __shared__ __align__(16) u64   sh_part[512];   // [grp=4][j=4][pair=32]    (4 KB)
    __shared__ __align__(16) float sh_hp[512];     // halt partials [warp=8][b=64]
    __shared__ float sh_hn[256];                   // current h slice [j=4][b=64]
    __shared__ float sh_cum[64];
    __shared__ float sh_w[64];
    __shared__ float sh_pond[64];
    __shared__ int   sh_halted[64];
    __shared__ float sh_whalt[4];
    __shared__ float sh_wih0[4];
    __shared__ float sh_bhalt;

    const int blk  = blockIdx.x;
    const int tid  = threadIdx.x;
    const int warp = tid >> 5, lane = tid & 31;
    const int half = lane >> 4, q = lane & 15;     // GEMM-internal half-warp split
    const int jo = warp & 3, b0 = lane * 2;        // output mapping (warps 4-7 shadow 0-3)
    const int gj = blk * 4 + jo;

    // one-time: W_hh slice (4 rows) -> SMEM dup-pairs, layout [k][j]
    for (int i = tid; i < 2048; i += 256) {
        int jj = i >> 9, k = i & 511;
        unsigned wb = __float_as_uint(W_hh[(blk * 4 + jj) * 512 + k]);
        sh_W2[k * 4 + jj] = ((u64)wb << 32) | (u64)wb;
    }
    if (tid < 4) {
        sh_whalt[tid] = W_halt[blk * 4 + tid];
        sh_wih0[tid]  = W_ih[(blk * 4 + tid) * 257];
    }
    if (tid == 0) sh_bhalt = b_halt[0];
    if (tid < 64) { sh_cum[tid] = 0.f; sh_pond[tid] = 0.f; sh_halted[tid] = 0; }
    __syncthreads();

    unsigned m = 0;               // global step counter (monotonic)
    int m3 = 0, nx3 = 1;          // m % 3, (m+1) % 3
    int t = 0, n = 0;             // timestep, local ponder index (uniform across blocks)
    float accx = 0.f, accy = 0.f; // acc_s for (jo, b0/b0+1)
    float hpx = 0.f, hpy = 0.f;   // previous-step h for (jo, b0/b0+1)

    unsigned* myflag = &g_flag[(((warp << 4) + (lane < 16 ? lane : 0)) << 5)];

    while (t < S_LEN) {
        // ---- prefetch this step's pre-projection BEFORE the wait ----
        const float2 pre2 = __ldg((const float2*)(g_preT + ((t * 512 + gj) << 6) + b0));
        // ---- phase 1: readiness check for this warp's 16 producers ----
        for (;;) {
            unsigned v = (lane < 16) ? ld_acq(myflag) : 0xffffffffu;
            if (__all_sync(0xffffffffu, v >= m)) break;
            __nanosleep(32);
        }
        // ---- GEMM: LDG.128 (2 k-rows/warp/load), acc[j][pair] per lane ----
        u64 a00=0,a01=0,a10=0,a11=0,a20=0,a21=0,a30=0,a31=0;
        {
            const ulonglong2* bufv = (const ulonglong2*)(g_hbuf + m3 * 65536 / 2);
            // note: m3*16384 u64 = m3*8192 ulonglong2; express directly:
            bufv = (const ulonglong2*)((const u64*)g_hbuf + m3 * 16384);
            #pragma unroll
            for (int c = 0; c < 32; ++c) {
                const int k = (warp << 6) + (c << 1) + half;
                ulonglong2 h4 = __ldcg(bufv + k * 16 + q);   // pairs (2q, 2q+1) of k-row
                const ulonglong2* wr = (const ulonglong2*)(sh_W2 + (k << 2));
                ulonglong2 w01 = wr[0], w23 = wr[1];
                ffma2(a00, h4.x, w01.x); ffma2(a01, h4.y, w01.x);
                ffma2(a10, h4.x, w01.y); ffma2(a11, h4.y, w01.y);
                ffma2(a20, h4.x, w23.x); ffma2(a21, h4.y, w23.x);
                ffma2(a30, h4.x, w23.y); ffma2(a31, h4.y, w23.y);
            }
            // fold the half-warp k-partition (lane L <-> L^16 hold same b, disjoint k)
            a00 = add2(a00, __shfl_xor_sync(0xffffffffu, a00, 16));
            a01 = add2(a01, __shfl_xor_sync(0xffffffffu, a01, 16));
            a10 = add2(a10, __shfl_xor_sync(0xffffffffu, a10, 16));
            a11 = add2(a11, __shfl_xor_sync(0xffffffffu, a11, 16));
            a20 = add2(a20, __shfl_xor_sync(0xffffffffu, a20, 16));
            a21 = add2(a21, __shfl_xor_sync(0xffffffffu, a21, 16));
            a30 = add2(a30, __shfl_xor_sync(0xffffffffu, a30, 16));
            a31 = add2(a31, __shfl_xor_sync(0xffffffffu, a31, 16));
        }
        // ---- haltv accumulate (float2, gated: unused at n==0) ----
        float2 hp2 = make_float2(0.f, 0.f);
        if (n >= 1) {
            const float2* hvr = (const float2*)(g_haltv + m3 * 8192);
            #pragma unroll
            for (int pc = 0; pc < 16; ++pc) {
                float2 v = __ldcg(hvr + (((warp << 4) + pc) << 5) + lane);
                hp2.x += v.x; hp2.y += v.y;
            }
        }
        // ---- stage K-partials (warps 0-3, lanes<16) + halt partials (all) ----
        if (warp < 4 && lane < 16) {
            u64* pp = sh_part + (warp << 7) + (q << 1);
            *(ulonglong2*)(pp + (0 << 5)) = make_ulonglong2(a00, a01);
            *(ulonglong2*)(pp + (1 << 5)) = make_ulonglong2(a10, a11);
            *(ulonglong2*)(pp + (2 << 5)) = make_ulonglong2(a20, a21);
            *(ulonglong2*)(pp + (3 << 5)) = make_ulonglong2(a30, a31);
        }
        *(float2*)(sh_hp + (warp << 6) + (lane << 1)) = hp2;
        __syncthreads();
        // ---- warps 4-7 fold; threads 0-63 finalize halting for q = n-1 ----
        if (warp >= 4 && lane < 16) {
            u64* pp = sh_part + ((warp - 4) << 7) + (q << 1);
            ulonglong2 v;
            v = *(ulonglong2*)(pp + (0 << 5));
            *(ulonglong2*)(pp + (0 << 5)) = make_ulonglong2(add2(v.x, a00), add2(v.y, a01));
            v = *(ulonglong2*)(pp + (1 << 5));
            *(ulonglong2*)(pp + (1 << 5)) = make_ulonglong2(add2(v.x, a10), add2(v.y, a11));
            v = *(ulonglong2*)(pp + (2 << 5));
            *(ulonglong2*)(pp + (2 << 5)) = make_ulonglong2(add2(v.x, a20), add2(v.y, a21));
            v = *(ulonglong2*)(pp + (3 << 5));
            *(ulonglong2*)(pp + (3 << 5)) = make_ulonglong2(add2(v.x, a30), add2(v.y, a31));
        }
        if (n >= 1 && tid < 64) {
            float s = 0.f;
            #pragma unroll
            for (int w8 = 0; w8 < 8; ++w8) s += sh_hp[(w8 << 6) + tid];   // fixed order
            float p = 1.f / (1.f + expf(-(s + sh_bhalt)));
            int hl = sh_halted[tid];
            if (hl) p = 0.f;
            float cum = sh_cum[tid];
            int is_h = (!hl) && (((cum + p) >= 0.99f) || (n - 1 == NMAX - 1));
            sh_w[tid] = is_h ? (1.f - cum) : p;
            if (is_h) sh_pond[tid] = (1.f - cum) + (float)n;   // (q+1) = n
            sh_cum[tid] = cum + p;
            sh_halted[tid] = hl | is_h;
        }
        int allh = __syncthreads_and((n == 0) ? 0 : (tid < 64 ? sh_halted[tid] : 1));
        // ---- acc update (lagged), then write h_new or carry (stores gated warp<4) ----
        {
            if (n >= 1) { accx += sh_w[b0] * hpx; accy += sh_w[b0 + 1] * hpy; }
            u64* bw = (u64*)g_hbuf + nx3 * 16384 + (gj << 5) + lane;
            if (!allh) {
                float sx = 0.f, sy = 0.f;
                #pragma unroll
                for (int g = 0; g < 4; ++g) {
                    u64 v = sh_part[(g << 7) + (jo << 5) + lane];
                    sx += lo32(v); sy += hi32(v);
                }
                float ax = sx + pre2.x, ay = sy + pre2.y;
                if (n == 0) { float f = sh_wih0[jo]; ax += f; ay += f; }
                float hx = tanhf(ax), hyv = tanhf(ay);
                hpx = hx; hpy = hyv;
                if (warp < 4) {
                    sh_hn[(jo << 6) + b0]     = hx;
                    sh_hn[(jo << 6) + b0 + 1] = hyv;
                    *bw = pack2(hx, hyv);
                }
            } else {
                if (warp < 4) *bw = pack2(accx, accy);   // carry = acc_s
            }
        }
        __syncthreads();
        // ---- publish halt vector (consumed next step) ----
        if (!allh && tid < 64) {
            float s = 0.f;
            #pragma unroll
            for (int jj = 0; jj < 4; ++jj) s += sh_whalt[jj] * sh_hn[(jj << 6) + tid];
            g_haltv[nx3 * 8192 + (blk << 6) + tid] = s;
        }
        __syncthreads();
        // ---- release this block's flag for step m+1 (critical path ends) ----
        if (tid == 0) st_rel(&g_flag[blk << 5], m + 1);
        // ---- off-path housekeeping ----
        if (!allh) {
            ++n;
        } else {
            if (warp < 4)
                *(float2*)(g_accsT + ((t * 512 + gj) << 6) + b0) = make_float2(accx, accy);
            if (blk == 0 && tid < 64) pond_out[t * 64 + tid] = sh_pond[tid];
            if (tid < 64) { sh_cum[tid] = 0.f; sh_pond[tid] = 0.f; sh_halted[tid] = 0; }
            accx = accy = 0.f;
            ++t; n = 0;
        }
        ++m;
        m3 = nx3; nx3 = (nx3 + 1 == 3) ? 0 : nx3 + 1;
    }
}

// ---------------- kernel 3: output GEMM ----------------
__global__ void __launch_bounds__(256) out_gemm(const float* __restrict__ W_out,
                                                const float* __restrict__ b_out,
                                                float* __restrict__ out) {
    __shared__ float As[64 * 65];
    __shared__ float Ws[64 * 65];
    const int t = blockIdx.y, ot = blockIdx.x;
    const int tid = threadIdx.x;
    const int ty = tid >> 4, tx = tid & 15;
    float acc[4][4] = {};
    for (int kc = 0; kc < 8; ++kc) {
        __syncthreads();
        for (int i = tid; i < 4096; i += 256) {
            int r = i >> 6, c = i & 63;
            As[r * 65 + c] = g_accsT[(t * 512 + kc * 64 + r) * 64 + c];
            Ws[r * 65 + c] = W_out[(ot * 64 + r) * 512 + kc * 64 + c];
        }
        __syncthreads();
        #pragma unroll 8
        for (int kk = 0; kk < 64; ++kk) {
            float wv[4], xv[4];
            #pragma unroll
            for (int a = 0; a < 4; ++a) wv[a] = Ws[(ty * 4 + a) * 65 + kk];
            #pragma unroll
            for (int c = 0; c < 4; ++c) xv[c] = As[kk * 65 + tx * 4 + c];
            #pragma unroll
            for (int a = 0; a < 4; ++a)
                #pragma unroll
                for (int c = 0; c < 4; ++c)
                    acc[a][c] = fmaf(wv[a], xv[c], acc[a][c]);
        }
    }
    #pragma unroll
    for (int a = 0; a < 4; ++a) {
        int o = ot * 64 + ty * 4 + a;
        float bias = b_out[o];
        #pragma unroll
        for (int c = 0; c < 4; ++c) {
            int b = tx * 4 + c;
            out[(t * 64 + b) * 256 + o] = acc[a][c] + bias;
        }
    }
}

extern "C" void kernel_launch(void* const* d_in, const int* in_sizes, int n_in,
                              void* d_out, int out_size) {
    const float* x      = (const float*)d_in[0];
    const float* s      = (const float*)d_in[1];
    const float* W_ih   = (const float*)d_in[2];
    const float* b_ih   = (const float*)d_in[3];
    const float* W_hh   = (const float*)d_in[4];
    const float* b_hh   = (const float*)d_in[5];
    const float* W_out  = (const float*)d_in[6];
    const float* b_out  = (const float*)d_in[7];
    const float* W_halt = (const float*)d_in[8];
    const float* b_halt = (const float*)d_in[9];
    float* out  = (float*)d_out;                       // outputs [S,B,O]
    float* pond = out + S_LEN * B_SZ * O_SZ;           // ponder  [S,B]

    dim3 preg(8, S_LEN);
    pre_gemm<<<preg, 256>>>(x, W_ih, b_ih, b_hh);
    init_h<<<B_SZ, H_SZ>>>(s);
    rnn_act<<<NBLK, 256>>>(W_hh, W_ih, W_halt, b_halt, pond);
    dim3 outg(4, S_LEN);
    out_gemm<<<outg, 256>>>(W_out, b_out, out);
}

// round 13
// speedup vs baseline: 1.3791x; 1.0018x over previous
#include <cuda_runtime.h>
#include <math.h>

#define S_LEN 128
#define B_SZ  64
#define H_SZ  512
#define O_SZ  256
#define NMAX  8
#define NBLK  128   // 64 j-groups x 2 batch-halves; each block = 8 j x 32 b

typedef unsigned long long u64;

// ---------------- device scratch (static; allocation is forbidden) ----------------
__device__ __align__(16) float g_preT[S_LEN * H_SZ * B_SZ];   // [t][j][b]
__device__ __align__(16) float g_accsT[S_LEN * H_SZ * B_SZ];  // [t][j][b]
__device__ __align__(16) float g_hbuf[3 * H_SZ * B_SZ];       // triple-buffer [buf][k][b]
__device__ __align__(16) float g_haltv[3 * 64 * B_SZ];        // [buf][jgrp=64][b=64]
__device__ unsigned g_flag[NBLK * 32];                        // per-block flag, 128B stride

__device__ __forceinline__ void ffma2(u64 &d, u64 a, u64 b) {
    asm("fma.rn.f32x2 %0, %1, %2, %0;" : "+l"(d) : "l"(a), "l"(b));
}
__device__ __forceinline__ u64 add2(u64 a, u64 b) {
    u64 r;
    asm("add.rn.f32x2 %0, %1, %2;" : "=l"(r) : "l"(a), "l"(b));
    return r;
}
__device__ __forceinline__ float lo32(u64 v) { return __uint_as_float((unsigned)(v & 0xffffffffu)); }
__device__ __forceinline__ float hi32(u64 v) { return __uint_as_float((unsigned)(v >> 32)); }
__device__ __forceinline__ u64 pack2(float x, float y) {
    return ((u64)__float_as_uint(y) << 32) | (u64)__float_as_uint(x);
}
__device__ __forceinline__ unsigned ld_acq(unsigned* p) {
    unsigned v;
    asm volatile("ld.acquire.gpu.u32 %0, [%1];" : "=r"(v) : "l"(p) : "memory");
    return v;
}
__device__ __forceinline__ void st_rel(unsigned* p, unsigned v) {
    asm volatile("st.release.gpu.u32 [%0], %1;" :: "l"(p), "r"(v) : "memory");
}

// ---------------- kernel 1: pre-projection GEMM ----------------
__global__ void __launch_bounds__(256) pre_gemm(const float* __restrict__ x,
                                                const float* __restrict__ W_ih,
                                                const float* __restrict__ b_ih,
                                                const float* __restrict__ b_hh) {
    __shared__ float Xs[64 * 65];
    __shared__ float Ws[64 * 65];
    const int t = blockIdx.y, jt = blockIdx.x;
    const int tid = threadIdx.x;
    const int ty = tid >> 4, tx = tid & 15;
    float acc[4][4] = {};
    for (int kc = 0; kc < 4; ++kc) {
        __syncthreads();
        for (int i = tid; i < 4096; i += 256) {
            int r = i >> 6, kk = i & 63;
            Xs[r * 65 + kk] = x[(t * 64 + r) * 256 + kc * 64 + kk];
            Ws[r * 65 + kk] = W_ih[(jt * 64 + r) * 257 + 1 + kc * 64 + kk];
        }
        __syncthreads();
        #pragma unroll 8
        for (int kk = 0; kk < 64; ++kk) {
            float wv[4], xv[4];
            #pragma unroll
            for (int a = 0; a < 4; ++a) wv[a] = Ws[(ty * 4 + a) * 65 + kk];
            #pragma unroll
            for (int c = 0; c < 4; ++c) xv[c] = Xs[(tx * 4 + c) * 65 + kk];
            #pragma unroll
            for (int a = 0; a < 4; ++a)
                #pragma unroll
                for (int c = 0; c < 4; ++c)
                    acc[a][c] = fmaf(wv[a], xv[c], acc[a][c]);
        }
    }
    #pragma unroll
    for (int a = 0; a < 4; ++a) {
        int j = jt * 64 + ty * 4 + a;
        float bias = b_ih[j] + b_hh[j];
        #pragma unroll
        for (int c = 0; c < 4; ++c) {
            int b = tx * 4 + c;
            g_preT[(t * 512 + j) * 64 + b] = acc[a][c] + bias;
        }
    }
}

// ---------------- init: s -> buf0 [k][b]; reset all 128 flags ----------------
__global__ void init_h(const float* __restrict__ s) {
    if (threadIdx.x < 2) g_flag[(blockIdx.x * 2 + threadIdx.x) * 32] = 0u;
    int b = blockIdx.x;
    int j = threadIdx.x;
    g_hbuf[j * 64 + b] = s[b * 512 + j];
}

// ---------------- kernel 2: persistent ACT recurrence (64 jgrp x 2 halves) ----------------
__global__ void __launch_bounds__(256, 1) rnn_act(const float* __restrict__ W_hh,
                                                  const float* __restrict__ W_ih,
                                                  const float* __restrict__ W_halt,
                                                  const float* __restrict__ b_halt,
                                                  float* __restrict__ pond_out) {
    __shared__ __align__(16) u64   sh_W2[4096];    // [k=512][j=8] dup-pairs (32 KB)
    __shared__ __align__(16) u64   sh_part[512];   // [grp=4][j=8][pair=16]     (4 KB)
    __shared__ __align__(16) float sh_hp[512];     // haltv partials [warp=8][b=64]
    __shared__ __align__(16) float2 sh_hw[64];     // [w=4][pair=16]
    __shared__ float sh_cum[64];
    __shared__ float sh_w[64];
    __shared__ float sh_pond[64];
    __shared__ int   sh_halted[64];
    __shared__ float sh_whalt[8];
    __shared__ float sh_wih0[8];
    __shared__ float sh_bhalt;

    const int blk  = blockIdx.x;
    const int jg   = blk >> 1, half = blk & 1;     // j-group, batch-half
    const int tid  = threadIdx.x;
    const int warp = tid >> 5, lane = tid & 31;
    const int r4 = lane >> 3, q = lane & 7;        // GEMM lane map: 4 k-rows x 8 pair-pairs
    const int jo = (warp << 1) + (lane >> 4);      // output map (warps 0-3): j 0..7
    const int po = lane & 15;                      // output pair 0..15
    const int b0 = (half << 5) + (po << 1);        // global batch index of output pair
    const int gjrow = jg * 8 + jo;                 // valid for warps 0-3 only

    // one-time: W_hh slice (8 rows) -> SMEM dup-pairs, layout [k][j]
    for (int i = tid; i < 4096; i += 256) {
        int jj = i >> 9, k = i & 511;
        unsigned wb = __float_as_uint(W_hh[(jg * 8 + jj) * 512 + k]);
        sh_W2[k * 8 + jj] = ((u64)wb << 32) | (u64)wb;
    }
    if (tid < 8) {
        sh_whalt[tid] = W_halt[jg * 8 + tid];
        sh_wih0[tid]  = W_ih[(jg * 8 + tid) * 257];
    }
    if (tid == 0) sh_bhalt = b_halt[0];
    if (tid < 64) { sh_cum[tid] = 0.f; sh_pond[tid] = 0.f; sh_halted[tid] = 0; }
    __syncthreads();

    unsigned m = 0;
    int m3 = 0, nx3 = 1;
    int t = 0, n = 0;                              // uniform across all blocks
    float accx = 0.f, accy = 0.f;                  // acc_s for (jo, b0/b0+1), warps 0-3
    float hpx = 0.f, hpy = 0.f;                    // previous-step h

    unsigned* myflag = &g_flag[(((warp << 4) + (lane < 16 ? lane : 0)) << 5)];

    while (t < S_LEN) {
        // ---- prefetch pre-projection (warps 0-3 only; others OOB-gated) ----
        float2 pre2 = make_float2(0.f, 0.f);
        if (warp < 4)
            pre2 = __ldg((const float2*)(g_preT + ((t * 512 + gjrow) << 6) + b0));
        // ---- wait: all 128 producers (16 flags per warp) ----
        for (;;) {
            unsigned v = (lane < 16) ? ld_acq(myflag) : 0xffffffffu;
            if (__all_sync(0xffffffffu, v >= m)) break;
            __nanosleep(32);
        }
        // ---- GEMM: 64 k per warp, 8 j, 32 b (this half). LDG.128 covers 4 b-pairs ----
        u64 acc[8][2] = {};
        {
            const ulonglong2* bufv = (const ulonglong2*)((const u64*)g_hbuf + m3 * 16384);
            #pragma unroll
            for (int c = 0; c < 16; ++c) {
                const int k = (warp << 6) + (c << 2) + r4;
                ulonglong2 h4 = __ldcg(bufv + k * 16 + (half << 3) + q);
                const ulonglong2* wr = (const ulonglong2*)(sh_W2 + (k << 3));
                ulonglong2 w01 = wr[0], w23 = wr[1], w45 = wr[2], w67 = wr[3];
                ffma2(acc[0][0], h4.x, w01.x); ffma2(acc[0][1], h4.y, w01.x);
                ffma2(acc[1][0], h4.x, w01.y); ffma2(acc[1][1], h4.y, w01.y);
                ffma2(acc[2][0], h4.x, w23.x); ffma2(acc[2][1], h4.y, w23.x);
                ffma2(acc[3][0], h4.x, w23.y); ffma2(acc[3][1], h4.y, w23.y);
                ffma2(acc[4][0], h4.x, w45.x); ffma2(acc[4][1], h4.y, w45.x);
                ffma2(acc[5][0], h4.x, w45.y); ffma2(acc[5][1], h4.y, w45.y);
                ffma2(acc[6][0], h4.x, w67.x); ffma2(acc[6][1], h4.y, w67.x);
                ffma2(acc[7][0], h4.x, w67.y); ffma2(acc[7][1], h4.y, w67.y);
            }
            // fold the 4-way k-split within the warp (r4 dimension: xor 8 then 16)
            #pragma unroll
            for (int jj = 0; jj < 8; ++jj) {
                #pragma unroll
                for (int pp = 0; pp < 2; ++pp) {
                    u64 v = acc[jj][pp];
                    v = add2(v, __shfl_xor_sync(0xffffffffu, v, 8));
                    v = add2(v, __shfl_xor_sync(0xffffffffu, v, 16));
                    acc[jj][pp] = v;
                }
            }
        }
        // ---- haltv accumulate: full [64 jgrp][64 b], 8 rows per warp (gated n==0) ----
        float2 hp2 = make_float2(0.f, 0.f);
        if (n >= 1) {
            const float2* hvr = (const float2*)(g_haltv + m3 * 4096);
            #pragma unroll
            for (int i = 0; i < 8; ++i) {
                float2 v = __ldcg(hvr + ((warp << 3) + i) * 32 + lane);
                hp2.x += v.x; hp2.y += v.y;
            }
        }
        // ---- stage: K-partials (warps 0-3, lanes<8) + haltv partials (all warps) ----
        if (warp < 4 && lane < 8) {
            ulonglong2* pp = (ulonglong2*)(sh_part + (warp << 7)) ;
            #pragma unroll
            for (int jj = 0; jj < 8; ++jj)
                pp[(jj << 3) + q] = make_ulonglong2(acc[jj][0], acc[jj][1]);
        }
        *(float2*)(sh_hp + (warp << 6) + (lane << 1)) = hp2;
        __syncthreads();                                               // S1
        // ---- warps 4-7 fold K-partials; threads 0-63 finalize halting for q=n-1 ----
        if (warp >= 4 && lane < 8) {
            ulonglong2* pp = (ulonglong2*)(sh_part + ((warp - 4) << 7));
            #pragma unroll
            for (int jj = 0; jj < 8; ++jj) {
                ulonglong2 v = pp[(jj << 3) + q];
                pp[(jj << 3) + q] = make_ulonglong2(add2(v.x, acc[jj][0]),
                                                    add2(v.y, acc[jj][1]));
            }
        }
        if (n >= 1 && tid < 64) {
            float s = 0.f;
            #pragma unroll
            for (int w8 = 0; w8 < 8; ++w8) s += sh_hp[(w8 << 6) + tid];   // fixed order
            float p = 1.f / (1.f + expf(-(s + sh_bhalt)));
            int hl = sh_halted[tid];
            if (hl) p = 0.f;
            float cum = sh_cum[tid];
            int is_h = (!hl) && (((cum + p) >= 0.99f) || (n - 1 == NMAX - 1));
            sh_w[tid] = is_h ? (1.f - cum) : p;
            if (is_h) sh_pond[tid] = (1.f - cum) + (float)n;   // (q+1) = n
            sh_cum[tid] = cum + p;
            sh_halted[tid] = hl | is_h;
        }
        int allh = __syncthreads_and((n == 0) ? 0 : (tid < 64 ? sh_halted[tid] : 1));  // S2
        // ---- output phase (warps 0-3 own the 128 cells) ----
        if (warp < 4) {
            if (n >= 1) { accx += sh_w[b0] * hpx; accy += sh_w[b0 + 1] * hpy; }
            u64* bw = (u64*)g_hbuf + nx3 * 16384 + gjrow * 32 + (half << 4) + po;
            if (!allh) {
                float sx = 0.f, sy = 0.f;
                #pragma unroll
                for (int g = 0; g < 4; ++g) {
                    u64 v = sh_part[(g << 7) + (jo << 4) + po];
                    sx += lo32(v); sy += hi32(v);
                }
                float ax = sx + pre2.x, ay = sy + pre2.y;
                if (n == 0) { float f = sh_wih0[jo]; ax += f; ay += f; }
                float hx = tanhf(ax), hyv = tanhf(ay);
                hpx = hx; hpy = hyv;
                *bw = pack2(hx, hyv);
                // in-warp fold of this warp's two j's (lanes po <-> po+16)
                float2 hw = make_float2(sh_whalt[jo] * hx, sh_whalt[jo] * hyv);
                hw.x += __shfl_xor_sync(0xffffffffu, hw.x, 16);
                hw.y += __shfl_xor_sync(0xffffffffu, hw.y, 16);
                if (lane < 16) sh_hw[(warp << 4) + po] = hw;
            } else {
                *bw = pack2(accx, accy);                       // carry = acc_s
            }
        }
        __syncthreads();                                               // S3
        // ---- warp 0: publish haltv (fold 4 warps) + release; ordered by syncwarp ----
        if (warp == 0) {
            if (!allh && lane < 16) {
                float2 s0 = sh_hw[lane],       s1 = sh_hw[16 + lane];
                float2 s2 = sh_hw[32 + lane],  s3 = sh_hw[48 + lane];
                float2 sv = make_float2(((s0.x + s1.x) + s2.x) + s3.x,
                                        ((s0.y + s1.y) + s2.y) + s3.y);
                ((float2*)(g_haltv + nx3 * 4096 + (jg << 6) + (half << 5)))[lane] = sv;
            }
            __syncwarp();
            if (lane == 0) st_rel(&g_flag[blk << 5], m + 1);
        }
        // ---- off-path housekeeping ----
        if (!allh) {
            ++n;
        } else {
            if (warp < 4)
                *(float2*)(g_accsT + ((t * 512 + gjrow) << 6) + b0) = make_float2(accx, accy);
            if (blk == 0 && tid < 64) pond_out[t * 64 + tid] = sh_pond[tid];
            if (tid < 64) { sh_cum[tid] = 0.f; sh_pond[tid] = 0.f; sh_halted[tid] = 0; }
            accx = accy = 0.f;
            ++t; n = 0;
        }
        ++m;
        m3 = nx3; nx3 = (nx3 + 1 == 3) ? 0 : nx3 + 1;
    }
}

// ---------------- kernel 3: output GEMM ----------------
__global__ void __launch_bounds__(256) out_gemm(const float* __restrict__ W_out,
                                                const float* __restrict__ b_out,
                                                float* __restrict__ out) {
    __shared__ float As[64 * 65];
    __shared__ float Ws[64 * 65];
    const int t = blockIdx.y, ot = blockIdx.x;
    const int tid = threadIdx.x;
    const int ty = tid >> 4, tx = tid & 15;
    float acc[4][4] = {};
    for (int kc = 0; kc < 8; ++kc) {
        __syncthreads();
        for (int i = tid; i < 4096; i += 256) {
            int r = i >> 6, c = i & 63;
            As[r * 65 + c] = g_accsT[(t * 512 + kc * 64 + r) * 64 + c];
            Ws[r * 65 + c] = W_out[(ot * 64 + r) * 512 + kc * 64 + c];
        }
        __syncthreads();
        #pragma unroll 8
        for (int kk = 0; kk < 64; ++kk) {
            float wv[4], xv[4];
            #pragma unroll
            for (int a = 0; a < 4; ++a) wv[a] = Ws[(ty * 4 + a) * 65 + kk];
            #pragma unroll
            for (int c = 0; c < 4; ++c) xv[c] = As[kk * 65 + tx * 4 + c];
            #pragma unroll
            for (int a = 0; a < 4; ++a)
                #pragma unroll
                for (int c = 0; c < 4; ++c)
                    acc[a][c] = fmaf(wv[a], xv[c], acc[a][c]);
        }
    }
    #pragma unroll
    for (int a = 0; a < 4; ++a) {
        int o = ot * 64 + ty * 4 + a;
        float bias = b_out[o];
        #pragma unroll
        for (int c = 0; c < 4; ++c) {
            int b = tx * 4 + c;
            out[(t * 64 + b) * 256 + o] = acc[a][c] + bias;
        }
    }
}

extern "C" void kernel_launch(void* const* d_in, const int* in_sizes, int n_in,
                              void* d_out, int out_size) {
    const float* x      = (const float*)d_in[0];
    const float* s      = (const float*)d_in[1];
    const float* W_ih   = (const float*)d_in[2];
    const float* b_ih   = (const float*)d_in[3];
    const float* W_hh   = (const float*)d_in[4];
    const float* b_hh   = (const float*)d_in[5];
    const float* W_out  = (const float*)d_in[6];
    const float* b_out  = (const float*)d_in[7];
    const float* W_halt = (const float*)d_in[8];
    const float* b_halt = (const float*)d_in[9];
    float* out  = (float*)d_out;                       // outputs [S,B,O]
    float* pond = out + S_LEN * B_SZ * O_SZ;           // ponder  [S,B]

    dim3 preg(8, S_LEN);
    pre_gemm<<<preg, 256>>>(x, W_ih, b_ih, b_hh);
    init_h<<<B_SZ, H_SZ>>>(s);
    rnn_act<<<NBLK, 256>>>(W_hh, W_ih, W_halt, b_halt, pond);
    dim3 outg(4, S_LEN);
    out_gemm<<<outg, 256>>>(W_out, b_out, out);
}

// round 14
// speedup vs baseline: 1.4100x; 1.0224x over previous
#include <cuda_runtime.h>
#include <math.h>

#define S_LEN 128
#define B_SZ  64
#define H_SZ  512
#define O_SZ  256
#define NMAX  8
#define NBLK  128   // 64 j-groups x 2 independent batch-half pipelines

typedef unsigned long long u64;

// ---------------- device scratch (static; allocation is forbidden) ----------------
__device__ __align__(16) float g_preT[S_LEN * H_SZ * B_SZ];   // [t][j][b]
__device__ __align__(16) float g_accsT[S_LEN * H_SZ * B_SZ];  // [t][j][b]
__device__ __align__(16) float g_hbuf[3 * H_SZ * B_SZ];       // [buf][k][b]; halves use disjoint b-slices
__device__ __align__(16) float g_haltv[3 * 2 * 256 * 32];     // [buf][half][jg*4+sub][b=32]
__device__ unsigned g_flag[NBLK * 32];                        // [half*64+jg], 128B stride

__device__ __forceinline__ void ffma2(u64 &d, u64 a, u64 b) {
    asm("fma.rn.f32x2 %0, %1, %2, %0;" : "+l"(d) : "l"(a), "l"(b));
}
__device__ __forceinline__ u64 add2(u64 a, u64 b) {
    u64 r;
    asm("add.rn.f32x2 %0, %1, %2;" : "=l"(r) : "l"(a), "l"(b));
    return r;
}
__device__ __forceinline__ float lo32(u64 v) { return __uint_as_float((unsigned)(v & 0xffffffffu)); }
__device__ __forceinline__ float hi32(u64 v) { return __uint_as_float((unsigned)(v >> 32)); }
__device__ __forceinline__ u64 pack2(float x, float y) {
    return ((u64)__float_as_uint(y) << 32) | (u64)__float_as_uint(x);
}
__device__ __forceinline__ unsigned ld_acq(unsigned* p) {
    unsigned v;
    asm volatile("ld.acquire.gpu.u32 %0, [%1];" : "=r"(v) : "l"(p) : "memory");
    return v;
}
__device__ __forceinline__ void st_rel(unsigned* p, unsigned v) {
    asm volatile("st.release.gpu.u32 [%0], %1;" :: "l"(p), "r"(v) : "memory");
}

// ---------------- kernel 1: pre-projection GEMM ----------------
__global__ void __launch_bounds__(256) pre_gemm(const float* __restrict__ x,
                                                const float* __restrict__ W_ih,
                                                const float* __restrict__ b_ih,
                                                const float* __restrict__ b_hh) {
    __shared__ float Xs[64 * 65];
    __shared__ float Ws[64 * 65];
    const int t = blockIdx.y, jt = blockIdx.x;
    const int tid = threadIdx.x;
    const int ty = tid >> 4, tx = tid & 15;
    float acc[4][4] = {};
    for (int kc = 0; kc < 4; ++kc) {
        __syncthreads();
        for (int i = tid; i < 4096; i += 256) {
            int r = i >> 6, kk = i & 63;
            Xs[r * 65 + kk] = x[(t * 64 + r) * 256 + kc * 64 + kk];
            Ws[r * 65 + kk] = W_ih[(jt * 64 + r) * 257 + 1 + kc * 64 + kk];
        }
        __syncthreads();
        #pragma unroll 8
        for (int kk = 0; kk < 64; ++kk) {
            float wv[4], xv[4];
            #pragma unroll
            for (int a = 0; a < 4; ++a) wv[a] = Ws[(ty * 4 + a) * 65 + kk];
            #pragma unroll
            for (int c = 0; c < 4; ++c) xv[c] = Xs[(tx * 4 + c) * 65 + kk];
            #pragma unroll
            for (int a = 0; a < 4; ++a)
                #pragma unroll
                for (int c = 0; c < 4; ++c)
                    acc[a][c] = fmaf(wv[a], xv[c], acc[a][c]);
        }
    }
    #pragma unroll
    for (int a = 0; a < 4; ++a) {
        int j = jt * 64 + ty * 4 + a;
        float bias = b_ih[j] + b_hh[j];
        #pragma unroll
        for (int c = 0; c < 4; ++c) {
            int b = tx * 4 + c;
            g_preT[(t * 512 + j) * 64 + b] = acc[a][c] + bias;
        }
    }
}

// ---------------- init: s -> buf0 [k][b]; reset all 128 flags ----------------
__global__ void init_h(const float* __restrict__ s) {
    if (threadIdx.x < 2) g_flag[(blockIdx.x * 2 + threadIdx.x) * 32] = 0u;
    int b = blockIdx.x;
    int j = threadIdx.x;
    g_hbuf[j * 64 + b] = s[b * 512 + j];
}

// ---------------- kernel 2: two decoupled half-pipelines (64 blocks each) ----------------
__global__ void __launch_bounds__(256, 1) rnn_act(const float* __restrict__ W_hh,
                                                  const float* __restrict__ W_ih,
                                                  const float* __restrict__ W_halt,
                                                  const float* __restrict__ b_halt,
                                                  float* __restrict__ pond_out) {
    __shared__ __align__(16) u64   sh_W2[4096];    // [k=512][j=8] dup-pairs (32 KB)
    __shared__ __align__(16) u64   sh_part[512];   // [grp=4][j=8][pair=16]     (4 KB)
    __shared__ __align__(16) float sh_hp[256];     // haltv partials [warp=8][b=32]
    __shared__ float sh_cum[32];
    __shared__ float sh_w[32];
    __shared__ float sh_pond[32];
    __shared__ int   sh_halted[32];
    __shared__ float sh_whalt[8];
    __shared__ float sh_wih0[8];
    __shared__ float sh_bhalt;

    const int blk  = blockIdx.x;
    const int jg   = blk >> 1, half = blk & 1;     // j-group, batch-half pipeline id
    const int tid  = threadIdx.x;
    const int warp = tid >> 5, lane = tid & 31;
    const int r4 = lane >> 3, q = lane & 7;        // GEMM lane map: 4 k-rows x 8 vec-chunks
    const int jo = (warp << 1) + (lane >> 4);      // output map (warps 0-3): j 0..7
    const int po = lane & 15;                      // output pair 0..15 (local b = 2po,2po+1)
    const int b0 = (half << 5) + (po << 1);        // global batch index of output pair
    const int gjrow = jg * 8 + jo;                 // valid for warps 0-3 only

    // one-time: W_hh slice (8 rows) -> SMEM dup-pairs, layout [k][j]
    for (int i = tid; i < 4096; i += 256) {
        int jj = i >> 9, k = i & 511;
        unsigned wb = __float_as_uint(W_hh[(jg * 8 + jj) * 512 + k]);
        sh_W2[k * 8 + jj] = ((u64)wb << 32) | (u64)wb;
    }
    if (tid < 8) {
        sh_whalt[tid] = W_halt[jg * 8 + tid];
        sh_wih0[tid]  = W_ih[(jg * 8 + tid) * 257];
    }
    if (tid == 0) sh_bhalt = b_halt[0];
    if (tid < 32) { sh_cum[tid] = 0.f; sh_pond[tid] = 0.f; sh_halted[tid] = 0; }
    __syncthreads();

    unsigned m = 0;                                // this HALF's step counter
    int m3 = 0, nx3 = 1;
    int t = 0, n = 0;                              // uniform within the half
    float accx = 0.f, accy = 0.f;                  // acc_s for (jo, b0/b0+1), warps 0-3
    float hpx = 0.f, hpy = 0.f;                    // previous-step h

    // this warp checks 8 of this half's 64 flags
    unsigned* myflag = &g_flag[((half << 6) + (warp << 3) + (lane < 8 ? lane : 0)) << 5];
    float* haltv_half = g_haltv;                   // indexed per-step below

    while (t < S_LEN) {
        // ---- prefetch pre-projection (warps 0-3 only) ----
        float2 pre2 = make_float2(0.f, 0.f);
        if (warp < 4)
            pre2 = __ldg((const float2*)(g_preT + ((t * 512 + gjrow) << 6) + b0));
        // ---- wait: 64 producers of THIS half (8 flags per warp) ----
        for (;;) {
            unsigned v = (lane < 8) ? ld_acq(myflag) : 0xffffffffu;
            if (__all_sync(0xffffffffu, v >= m)) break;
            __nanosleep(32);
        }
        // ---- GEMM: 64 k per warp, 8 j, 32 b (this half) ----
        u64 acc[8][2] = {};
        {
            const ulonglong2* bufv = (const ulonglong2*)((const u64*)g_hbuf + m3 * 16384);
            #pragma unroll
            for (int c = 0; c < 16; ++c) {
                const int k = (warp << 6) + (c << 2) + r4;
                ulonglong2 h4 = __ldcg(bufv + k * 16 + (half << 3) + q);
                const ulonglong2* wr = (const ulonglong2*)(sh_W2 + (k << 3));
                ulonglong2 w01 = wr[0], w23 = wr[1], w45 = wr[2], w67 = wr[3];
                ffma2(acc[0][0], h4.x, w01.x); ffma2(acc[0][1], h4.y, w01.x);
                ffma2(acc[1][0], h4.x, w01.y); ffma2(acc[1][1], h4.y, w01.y);
                ffma2(acc[2][0], h4.x, w23.x); ffma2(acc[2][1], h4.y, w23.x);
                ffma2(acc[3][0], h4.x, w23.y); ffma2(acc[3][1], h4.y, w23.y);
                ffma2(acc[4][0], h4.x, w45.x); ffma2(acc[4][1], h4.y, w45.x);
                ffma2(acc[5][0], h4.x, w45.y); ffma2(acc[5][1], h4.y, w45.y);
                ffma2(acc[6][0], h4.x, w67.x); ffma2(acc[6][1], h4.y, w67.x);
                ffma2(acc[7][0], h4.x, w67.y); ffma2(acc[7][1], h4.y, w67.y);
            }
            #pragma unroll
            for (int jj = 0; jj < 8; ++jj) {
                #pragma unroll
                for (int pp = 0; pp < 2; ++pp) {
                    u64 v = acc[jj][pp];
                    v = add2(v, __shfl_xor_sync(0xffffffffu, v, 8));
                    v = add2(v, __shfl_xor_sync(0xffffffffu, v, 16));
                    acc[jj][pp] = v;
                }
            }
        }
        // ---- haltv consumer: 256 partial rows of 32 b, 32 rows per warp (gated) ----
        float2 hp2 = make_float2(0.f, 0.f);
        if (n >= 1) {
            const float2* hvr = (const float2*)(haltv_half + (m3 * 2 + half) * 8192);
            const int rbase = (warp << 5) + (lane >> 4);
            const int fi = lane & 15;
            #pragma unroll
            for (int i = 0; i < 16; ++i) {
                float2 v = __ldcg(hvr + (rbase + (i << 1)) * 16 + fi);
                hp2.x += v.x; hp2.y += v.y;
            }
            // combine the two row-parities (lane L <-> L^16 share the same b-pair)
            hp2.x += __shfl_xor_sync(0xffffffffu, hp2.x, 16);
            hp2.y += __shfl_xor_sync(0xffffffffu, hp2.y, 16);
        }
        // ---- stage: K-partials (warps 0-3, lanes<8) + haltv partials (lanes<16) ----
        if (warp < 4 && lane < 8) {
            ulonglong2* pp = (ulonglong2*)(sh_part + (warp << 7));
            #pragma unroll
            for (int jj = 0; jj < 8; ++jj)
                pp[(jj << 3) + q] = make_ulonglong2(acc[jj][0], acc[jj][1]);
        }
        if (lane < 16) *(float2*)(sh_hp + (warp << 5) + (lane << 1)) = hp2;
        __syncthreads();                                               // S1
        // ---- warps 4-7 fold K-partials; threads 0-31 finalize halting for q=n-1 ----
        if (warp >= 4 && lane < 8) {
            ulonglong2* pp = (ulonglong2*)(sh_part + ((warp - 4) << 7));
            #pragma unroll
            for (int jj = 0; jj < 8; ++jj) {
                ulonglong2 v = pp[(jj << 3) + q];
                pp[(jj << 3) + q] = make_ulonglong2(add2(v.x, acc[jj][0]),
                                                    add2(v.y, acc[jj][1]));
            }
        }
        if (n >= 1 && tid < 32) {
            float s = 0.f;
            #pragma unroll
            for (int w8 = 0; w8 < 8; ++w8) s += sh_hp[(w8 << 5) + tid];   // fixed order
            float p = 1.f / (1.f + expf(-(s + sh_bhalt)));
            int hl = sh_halted[tid];
            if (hl) p = 0.f;
            float cum = sh_cum[tid];
            int is_h = (!hl) && (((cum + p) >= 0.99f) || (n - 1 == NMAX - 1));
            sh_w[tid] = is_h ? (1.f - cum) : p;
            if (is_h) sh_pond[tid] = (1.f - cum) + (float)n;   // (q+1) = n
            sh_cum[tid] = cum + p;
            sh_halted[tid] = hl | is_h;
        }
        int allh = __syncthreads_and((n == 0) ? 0 : (tid < 32 ? sh_halted[tid] : 1));  // S2
        // ---- output phase (warps 0-3 own the 128 cells); warps 4-7 fall through ----
        if (warp < 4) {
            if (n >= 1) { accx += sh_w[po << 1] * hpx; accy += sh_w[(po << 1) + 1] * hpy; }
            u64* bw = (u64*)g_hbuf + nx3 * 16384 + gjrow * 32 + (half << 4) + po;
            if (!allh) {
                float sx = 0.f, sy = 0.f;
                #pragma unroll
                for (int g = 0; g < 4; ++g) {
                    u64 v = sh_part[(g << 7) + (jo << 4) + po];
                    sx += lo32(v); sy += hi32(v);
                }
                float ax = sx + pre2.x, ay = sy + pre2.y;
                if (n == 0) { float f = sh_wih0[jo]; ax += f; ay += f; }
                float hx = tanhf(ax), hyv = tanhf(ay);
                hpx = hx; hpy = hyv;
                *bw = pack2(hx, hyv);
                // fold this warp's 2 j via shfl; lanes<16 publish the warp's partial row
                float2 hw = make_float2(sh_whalt[jo] * hx, sh_whalt[jo] * hyv);
                hw.x += __shfl_xor_sync(0xffffffffu, hw.x, 16);
                hw.y += __shfl_xor_sync(0xffffffffu, hw.y, 16);
                if (lane < 16) {
                    float2* hvw = (float2*)(haltv_half + (nx3 * 2 + half) * 8192);
                    hvw[((jg << 2) + warp) * 16 + po] = hw;
                }
            } else {
                *bw = pack2(accx, accy);                       // carry = acc_s
            }
            asm volatile("bar.sync 1, 128;" ::: "memory");     // warps 0-3 only
            if (tid == 0) st_rel(&g_flag[((half << 6) + jg) << 5], m + 1);
        }
        // ---- off-path housekeeping (uniform across the half) ----
        if (!allh) {
            ++n;
        } else {
            if (warp < 4)
                *(float2*)(g_accsT + ((t * 512 + gjrow) << 6) + b0) = make_float2(accx, accy);
            if (jg == 0 && tid < 32) pond_out[t * 64 + (half << 5) + tid] = sh_pond[tid];
            if (tid < 32) { sh_cum[tid] = 0.f; sh_pond[tid] = 0.f; sh_halted[tid] = 0; }
            accx = accy = 0.f;
            ++t; n = 0;
        }
        ++m;
        m3 = nx3; nx3 = (nx3 + 1 == 3) ? 0 : nx3 + 1;
    }
}

// ---------------- kernel 3: output GEMM ----------------
__global__ void __launch_bounds__(256) out_gemm(const float* __restrict__ W_out,
                                                const float* __restrict__ b_out,
                                                float* __restrict__ out) {
    __shared__ float As[64 * 65];
    __shared__ float Ws[64 * 65];
    const int t = blockIdx.y, ot = blockIdx.x;
    const int tid = threadIdx.x;
    const int ty = tid >> 4, tx = tid & 15;
    float acc[4][4] = {};
    for (int kc = 0; kc < 8; ++kc) {
        __syncthreads();
        for (int i = tid; i < 4096; i += 256) {
            int r = i >> 6, c = i & 63;
            As[r * 65 + c] = g_accsT[(t * 512 + kc * 64 + r) * 64 + c];
            Ws[r * 65 + c] = W_out[(ot * 64 + r) * 512 + kc * 64 + c];
        }
        __syncthreads();
        #pragma unroll 8
        for (int kk = 0; kk < 64; ++kk) {
            float wv[4], xv[4];
            #pragma unroll
            for (int a = 0; a < 4; ++a) wv[a] = Ws[(ty * 4 + a) * 65 + kk];
            #pragma unroll
            for (int c = 0; c < 4; ++c) xv[c] = As[kk * 65 + tx * 4 + c];
            #pragma unroll
            for (int a = 0; a < 4; ++a)
                #pragma unroll
                for (int c = 0; c < 4; ++c)
                    acc[a][c] = fmaf(wv[a], xv[c], acc[a][c]);
        }
    }
    #pragma unroll
    for (int a = 0; a < 4; ++a) {
        int o = ot * 64 + ty * 4 + a;
        float bias = b_out[o];
        #pragma unroll
        for (int c = 0; c < 4; ++c) {
            int b = tx * 4 + c;
            out[(t * 64 + b) * 256 + o] = acc[a][c] + bias;
        }
    }
}

extern "C" void kernel_launch(void* const* d_in, const int* in_sizes, int n_in,
                              void* d_out, int out_size) {
    const float* x      = (const float*)d_in[0];
    const float* s      = (const float*)d_in[1];
    const float* W_ih   = (const float*)d_in[2];
    const float* b_ih   = (const float*)d_in[3];
    const float* W_hh   = (const float*)d_in[4];
    const float* b_hh   = (const float*)d_in[5];
    const float* W_out  = (const float*)d_in[6];
    const float* b_out  = (const float*)d_in[7];
    const float* W_halt = (const float*)d_in[8];
    const float* b_halt = (const float*)d_in[9];
    float* out  = (float*)d_out;                       // outputs [S,B,O]
    float* pond = out + S_LEN * B_SZ * O_SZ;           // ponder  [S,B]

    dim3 preg(8, S_LEN);
    pre_gemm<<<preg, 256>>>(x, W_ih, b_ih, b_hh);
    init_h<<<B_SZ, H_SZ>>>(s);
    rnn_act<<<NBLK, 256>>>(W_hh, W_ih, W_halt, b_halt, pond);
    dim3 outg(4, S_LEN);
    out_gemm<<<outg, 256>>>(W_out, b_out, out);
}

// round 15
// speedup vs baseline: 1.5507x; 1.0998x over previous
#include <cuda_runtime.h>
#include <math.h>

#define S_LEN 128
#define B_SZ  64
#define H_SZ  512
#define O_SZ  256
#define NMAX  8
#define NBLK  128   // 64 j-groups x 2 independent batch-half pipelines

typedef unsigned long long u64;

// ---------------- device scratch (static; allocation is forbidden) ----------------
__device__ __align__(16) float g_preT[S_LEN * H_SZ * B_SZ];   // [t][j][b]
__device__ __align__(16) float g_accsT[S_LEN * H_SZ * B_SZ];  // [t][j][b]
__device__ __align__(16) float g_hbuf[3 * H_SZ * B_SZ];       // [buf][k][b]
__device__ __align__(16) float g_haltv[3 * 2 * 256 * 32];     // [buf][half][jg*4+sub][b=32]
__device__ unsigned g_flag[NBLK * 32];                        // [half*64+jg], 128B stride

__device__ __forceinline__ void ffma2(u64 &d, u64 a, u64 b) {
    asm("fma.rn.f32x2 %0, %1, %2, %0;" : "+l"(d) : "l"(a), "l"(b));
}
__device__ __forceinline__ u64 add2(u64 a, u64 b) {
    u64 r;
    asm("add.rn.f32x2 %0, %1, %2;" : "=l"(r) : "l"(a), "l"(b));
    return r;
}
__device__ __forceinline__ float lo32(u64 v) { return __uint_as_float((unsigned)(v & 0xffffffffu)); }
__device__ __forceinline__ float hi32(u64 v) { return __uint_as_float((unsigned)(v >> 32)); }
__device__ __forceinline__ u64 pack2(float x, float y) {
    return ((u64)__float_as_uint(y) << 32) | (u64)__float_as_uint(x);
}
__device__ __forceinline__ unsigned ld_acq(unsigned* p) {
    unsigned v;
    asm volatile("ld.acquire.gpu.u32 %0, [%1];" : "=r"(v) : "l"(p) : "memory");
    return v;
}
__device__ __forceinline__ void st_rel(unsigned* p, unsigned v) {
    asm volatile("st.release.gpu.u32 [%0], %1;" :: "l"(p), "r"(v) : "memory");
}

// ---------------- kernel 1: pre-projection GEMM ----------------
__global__ void __launch_bounds__(256) pre_gemm(const float* __restrict__ x,
                                                const float* __restrict__ W_ih,
                                                const float* __restrict__ b_ih,
                                                const float* __restrict__ b_hh) {
    __shared__ float Xs[64 * 65];
    __shared__ float Ws[64 * 65];
    const int t = blockIdx.y, jt = blockIdx.x;
    const int tid = threadIdx.x;
    const int ty = tid >> 4, tx = tid & 15;
    float acc[4][4] = {};
    for (int kc = 0; kc < 4; ++kc) {
        __syncthreads();
        for (int i = tid; i < 4096; i += 256) {
            int r = i >> 6, kk = i & 63;
            Xs[r * 65 + kk] = x[(t * 64 + r) * 256 + kc * 64 + kk];
            Ws[r * 65 + kk] = W_ih[(jt * 64 + r) * 257 + 1 + kc * 64 + kk];
        }
        __syncthreads();
        #pragma unroll 8
        for (int kk = 0; kk < 64; ++kk) {
            float wv[4], xv[4];
            #pragma unroll
            for (int a = 0; a < 4; ++a) wv[a] = Ws[(ty * 4 + a) * 65 + kk];
            #pragma unroll
            for (int c = 0; c < 4; ++c) xv[c] = Xs[(tx * 4 + c) * 65 + kk];
            #pragma unroll
            for (int a = 0; a < 4; ++a)
                #pragma unroll
                for (int c = 0; c < 4; ++c)
                    acc[a][c] = fmaf(wv[a], xv[c], acc[a][c]);
        }
    }
    #pragma unroll
    for (int a = 0; a < 4; ++a) {
        int j = jt * 64 + ty * 4 + a;
        float bias = b_ih[j] + b_hh[j];
        #pragma unroll
        for (int c = 0; c < 4; ++c) {
            int b = tx * 4 + c;
            g_preT[(t * 512 + j) * 64 + b] = acc[a][c] + bias;
        }
    }
}

// ---------------- init: s -> buf0 [k][b]; reset all 128 flags ----------------
__global__ void init_h(const float* __restrict__ s) {
    if (threadIdx.x < 2) g_flag[(blockIdx.x * 2 + threadIdx.x) * 32] = 0u;
    int b = blockIdx.x;
    int j = threadIdx.x;
    g_hbuf[j * 64 + b] = s[b * 512 + j];
}

// ---------------- kernel 2: two decoupled half-pipelines, fast-carry ----------------
__global__ void __launch_bounds__(256, 1) rnn_act(const float* __restrict__ W_hh,
                                                  const float* __restrict__ W_ih,
                                                  const float* __restrict__ W_halt,
                                                  const float* __restrict__ b_halt,
                                                  float* __restrict__ pond_out) {
    __shared__ __align__(16) u64   sh_W2[4096];    // [k=512][j=8] dup-pairs (32 KB)
    __shared__ __align__(16) u64   sh_part[1024];  // [grp=8][j=8][pair=16]     (8 KB)
    __shared__ __align__(16) float sh_hp[256];     // haltv partials [warp=8][b=32]
    __shared__ float sh_whalt[8];
    __shared__ float sh_wih0[8];
    __shared__ float sh_bhalt;

    const int blk  = blockIdx.x;
    const int jg   = blk >> 1, half = blk & 1;     // j-group, batch-half pipeline id
    const int tid  = threadIdx.x;
    const int warp = tid >> 5, lane = tid & 31;
    const int r4 = lane >> 3, q = lane & 7;        // GEMM lane map: 4 k-rows x 8 vec-chunks
    const int jo = (warp << 1) + (lane >> 4);      // output map (warps 0-3): j 0..7
    const int po = lane & 15;                      // pair 0..15 (local b = 2po, 2po+1)
    const int b0 = (half << 5) + (po << 1);        // global batch index of output pair
    const int gjrow = jg * 8 + jo;                 // valid for warps 0-3 only

    // one-time: W_hh slice (8 rows) -> SMEM dup-pairs, layout [k][j]
    for (int i = tid; i < 4096; i += 256) {
        int jj = i >> 9, k = i & 511;
        unsigned wb = __float_as_uint(W_hh[(jg * 8 + jj) * 512 + k]);
        sh_W2[k * 8 + jj] = ((u64)wb << 32) | (u64)wb;
    }
    if (tid < 8) {
        sh_whalt[tid] = W_halt[jg * 8 + tid];
        sh_wih0[tid]  = W_ih[(jg * 8 + tid) * 257];
    }
    if (tid == 0) sh_bhalt = b_halt[0];
    __syncthreads();

    unsigned m = 0;                                // this HALF's step counter
    int m3 = 0, nx3 = 1;
    int t = 0, n = 0;                              // uniform within the half
    float accx = 0.f, accy = 0.f;                  // acc_s (warps 0-3)
    float hpx = 0.f, hpy = 0.f;                    // previous-step h (warps 0-3)
    float cumx = 0.f, cumy = 0.f;                  // replicated halt state (pair po)
    int   hlx = 0, hly = 0;
    float pondx = 0.f, pondy = 0.f;

    unsigned* myflag = &g_flag[((half << 6) + (warp << 3) + (lane < 8 ? lane : 0)) << 5];

    while (t < S_LEN) {
        // ---- prefetch pre-projection (warps 0-3 only) ----
        float2 pre2 = make_float2(0.f, 0.f);
        if (warp < 4)
            pre2 = __ldg((const float2*)(g_preT + ((t * 512 + gjrow) << 6) + b0));
        // ---- wait: 64 producers of THIS half (8 flags per warp) ----
        for (;;) {
            unsigned v = (lane < 8) ? ld_acq(myflag) : 0xffffffffu;
            if (__all_sync(0xffffffffu, v >= m)) break;
            __nanosleep(32);
        }
        // ---- up-front loads: h (always) + haltv (n>=1), maximum overlap ----
        ulonglong2 h4[16];
        {
            const ulonglong2* bufv = (const ulonglong2*)((const u64*)g_hbuf + m3 * 16384);
            #pragma unroll
            for (int c = 0; c < 16; ++c)
                h4[c] = __ldcg(bufv + ((warp << 6) + (c << 2) + r4) * 16 + (half << 3) + q);
        }
        float2 hp2 = make_float2(0.f, 0.f);
        if (n >= 1) {
            const float2* hvr = (const float2*)(g_haltv + (m3 * 2 + half) * 8192);
            const int rbase = (warp << 5) + (lane >> 4);
            const int fi = lane & 15;
            #pragma unroll
            for (int i = 0; i < 16; ++i) {
                float2 v = __ldcg(hvr + (rbase + (i << 1)) * 16 + fi);
                hp2.x += v.x; hp2.y += v.y;
            }
            hp2.x += __shfl_xor_sync(0xffffffffu, hp2.x, 16);
            hp2.y += __shfl_xor_sync(0xffffffffu, hp2.y, 16);
        }
        if (lane < 16) *(float2*)(sh_hp + (warp << 5) + (lane << 1)) = hp2;
        __syncthreads();                                               // S1
        // ---- replicated halt decision (all warps, identical inputs/order) ----
        int allh = 0;
        if (n >= 1) {
            float sx = 0.f, sy = 0.f;
            #pragma unroll
            for (int w8 = 0; w8 < 8; ++w8) {
                float2 v = *(const float2*)(sh_hp + (w8 << 5) + (po << 1));
                sx += v.x; sy += v.y;
            }
            float px = 1.f / (1.f + expf(-(sx + sh_bhalt)));
            float py = 1.f / (1.f + expf(-(sy + sh_bhalt)));
            if (hlx) px = 0.f;
            if (hly) py = 0.f;
            int ihx = (!hlx) && (((cumx + px) >= 0.99f) || (n - 1 == NMAX - 1));
            int ihy = (!hly) && (((cumy + py) >= 0.99f) || (n - 1 == NMAX - 1));
            float wx = ihx ? (1.f - cumx) : px;
            float wy = ihy ? (1.f - cumy) : py;
            if (ihx) pondx = (1.f - cumx) + (float)n;
            if (ihy) pondy = (1.f - cumy) + (float)n;
            cumx += px; cumy += py;
            hlx |= ihx; hly |= ihy;
            if (warp < 4) { accx += wx * hpx; accy += wy * hpy; }
            allh = __all_sync(0xffffffffu, hlx && hly);
        }
        if (!allh) {
            // ---- GEMM on preloaded h ----
            u64 acc[8][2] = {};
            #pragma unroll
            for (int c = 0; c < 16; ++c) {
                const int k = (warp << 6) + (c << 2) + r4;
                ulonglong2 h2v = h4[c];
                const ulonglong2* wr = (const ulonglong2*)(sh_W2 + (k << 3));
                ulonglong2 w01 = wr[0], w23 = wr[1], w45 = wr[2], w67 = wr[3];
                ffma2(acc[0][0], h2v.x, w01.x); ffma2(acc[0][1], h2v.y, w01.x);
                ffma2(acc[1][0], h2v.x, w01.y); ffma2(acc[1][1], h2v.y, w01.y);
                ffma2(acc[2][0], h2v.x, w23.x); ffma2(acc[2][1], h2v.y, w23.x);
                ffma2(acc[3][0], h2v.x, w23.y); ffma2(acc[3][1], h2v.y, w23.y);
                ffma2(acc[4][0], h2v.x, w45.x); ffma2(acc[4][1], h2v.y, w45.x);
                ffma2(acc[5][0], h2v.x, w45.y); ffma2(acc[5][1], h2v.y, w45.y);
                ffma2(acc[6][0], h2v.x, w67.x); ffma2(acc[6][1], h2v.y, w67.x);
                ffma2(acc[7][0], h2v.x, w67.y); ffma2(acc[7][1], h2v.y, w67.y);
            }
            #pragma unroll
            for (int jj = 0; jj < 8; ++jj) {
                #pragma unroll
                for (int pp = 0; pp < 2; ++pp) {
                    u64 v = acc[jj][pp];
                    v = add2(v, __shfl_xor_sync(0xffffffffu, v, 8));
                    v = add2(v, __shfl_xor_sync(0xffffffffu, v, 16));
                    acc[jj][pp] = v;
                }
            }
            // stage all 8 groups (no second-stage fold)
            if (lane < 8) {
                ulonglong2* pp = (ulonglong2*)(sh_part + (warp << 7));
                #pragma unroll
                for (int jj = 0; jj < 8; ++jj)
                    pp[(jj << 3) + q] = make_ulonglong2(acc[jj][0], acc[jj][1]);
            }
            __syncthreads();                                           // S2
            if (warp < 4) {
                float sx = 0.f, sy = 0.f;
                #pragma unroll
                for (int g = 0; g < 8; ++g) {
                    u64 v = sh_part[(g << 7) + (jo << 4) + po];
                    sx += lo32(v); sy += hi32(v);
                }
                float ax = sx + pre2.x, ay = sy + pre2.y;
                if (n == 0) { float f = sh_wih0[jo]; ax += f; ay += f; }
                float hx = tanhf(ax), hyv = tanhf(ay);
                hpx = hx; hpy = hyv;
                *((u64*)g_hbuf + nx3 * 16384 + gjrow * 32 + (half << 4) + po) = pack2(hx, hyv);
                float2 hw = make_float2(sh_whalt[jo] * hx, sh_whalt[jo] * hyv);
                hw.x += __shfl_xor_sync(0xffffffffu, hw.x, 16);
                hw.y += __shfl_xor_sync(0xffffffffu, hw.y, 16);
                if (lane < 16) {
                    float2* hvw = (float2*)(g_haltv + (nx3 * 2 + half) * 8192);
                    hvw[((jg << 2) + warp) * 16 + po] = hw;
                }
            }
        } else {
            // ---- fast-carry: no GEMM, no staging, no S2 ----
            if (warp < 4)
                *((u64*)g_hbuf + nx3 * 16384 + gjrow * 32 + (half << 4) + po) = pack2(accx, accy);
        }
        if (warp < 4) {
            asm volatile("bar.sync 1, 128;" ::: "memory");     // warps 0-3 only
            if (tid == 0) st_rel(&g_flag[((half << 6) + jg) << 5], m + 1);
        }
        // ---- off-path housekeeping ----
        if (!allh) {
            ++n;
        } else {
            if (warp < 4)
                *(float2*)(g_accsT + ((t * 512 + gjrow) << 6) + b0) = make_float2(accx, accy);
            if (jg == 0 && warp == 0 && lane < 16)
                *(float2*)(pond_out + t * 64 + (half << 5) + (po << 1)) = make_float2(pondx, pondy);
            cumx = cumy = 0.f; hlx = hly = 0; pondx = pondy = 0.f;
            accx = accy = 0.f;
            ++t; n = 0;
        }
        ++m;
        m3 = nx3; nx3 = (nx3 + 1 == 3) ? 0 : nx3 + 1;
    }
}

// ---------------- kernel 3: output GEMM ----------------
__global__ void __launch_bounds__(256) out_gemm(const float* __restrict__ W_out,
                                                const float* __restrict__ b_out,
                                                float* __restrict__ out) {
    __shared__ float As[64 * 65];
    __shared__ float Ws[64 * 65];
    const int t = blockIdx.y, ot = blockIdx.x;
    const int tid = threadIdx.x;
    const int ty = tid >> 4, tx = tid & 15;
    float acc[4][4] = {};
    for (int kc = 0; kc < 8; ++kc) {
        __syncthreads();
        for (int i = tid; i < 4096; i += 256) {
            int r = i >> 6, c = i & 63;
            As[r * 65 + c] = g_accsT[(t * 512 + kc * 64 + r) * 64 + c];
            Ws[r * 65 + c] = W_out[(ot * 64 + r) * 512 + kc * 64 + c];
        }
        __syncthreads();
        #pragma unroll 8
        for (int kk = 0; kk < 64; ++kk) {
            float wv[4], xv[4];
            #pragma unroll
            for (int a = 0; a < 4; ++a) wv[a] = Ws[(ty * 4 + a) * 65 + kk];
            #pragma unroll
            for (int c = 0; c < 4; ++c) xv[c] = As[kk * 65 + tx * 4 + c];
            #pragma unroll
            for (int a = 0; a < 4; ++a)
                #pragma unroll
                for (int c = 0; c < 4; ++c)
                    acc[a][c] = fmaf(wv[a], xv[c], acc[a][c]);
        }
    }
    #pragma unroll
    for (int a = 0; a < 4; ++a) {
        int o = ot * 64 + ty * 4 + a;
        float bias = b_out[o];
        #pragma unroll
        for (int c = 0; c < 4; ++c) {
            int b = tx * 4 + c;
            out[(t * 64 + b) * 256 + o] = acc[a][c] + bias;
        }
    }
}

extern "C" void kernel_launch(void* const* d_in, const int* in_sizes, int n_in,
                              void* d_out, int out_size) {
    const float* x      = (const float*)d_in[0];
    const float* s      = (const float*)d_in[1];
    const float* W_ih   = (const float*)d_in[2];
    const float* b_ih   = (const float*)d_in[3];
    const float* W_hh   = (const float*)d_in[4];
    const float* b_hh   = (const float*)d_in[5];
    const float* W_out  = (const float*)d_in[6];
    const float* b_out  = (const float*)d_in[7];
    const float* W_halt = (const float*)d_in[8];
    const float* b_halt = (const float*)d_in[9];
    float* out  = (float*)d_out;                       // outputs [S,B,O]
    float* pond = out + S_LEN * B_SZ * O_SZ;           // ponder  [S,B]

    dim3 preg(8, S_LEN);
    pre_gemm<<<preg, 256>>>(x, W_ih, b_ih, b_hh);
    init_h<<<B_SZ, H_SZ>>>(s);
    rnn_act<<<NBLK, 256>>>(W_hh, W_ih, W_halt, b_halt, pond);
    dim3 outg(4, S_LEN);
    out_gemm<<<outg, 256>>>(W_out, b_out, out);
}

// round 16
// speedup vs baseline: 1.6060x; 1.0356x over previous
#include <cuda_runtime.h>
#include <math.h>

#define S_LEN 128
#define B_SZ  64
#define H_SZ  512
#define O_SZ  256
#define NMAX  8
#define NBLK  128   // 64 j-groups x 2 independent batch-half pipelines

typedef unsigned long long u64;

// ---------------- device scratch (static; allocation is forbidden) ----------------
__device__ __align__(16) float g_preT[S_LEN * H_SZ * B_SZ];   // [t][j][b]
__device__ __align__(16) float g_accsT[S_LEN * H_SZ * B_SZ];  // [t][j][b]
__device__ __align__(16) float g_hbuf[3 * H_SZ * B_SZ];       // [buf][k][b]
__device__ __align__(16) float g_haltv[3 * 2 * 256 * 32];     // [buf][half][jg*4+sub][b=32]
__device__ unsigned g_flag[NBLK * 32];                        // [half*64+jg], 128B stride

__device__ __forceinline__ void ffma2(u64 &d, u64 a, u64 b) {
    asm("fma.rn.f32x2 %0, %1, %2, %0;" : "+l"(d) : "l"(a), "l"(b));
}
__device__ __forceinline__ u64 add2(u64 a, u64 b) {
    u64 r;
    asm("add.rn.f32x2 %0, %1, %2;" : "=l"(r) : "l"(a), "l"(b));
    return r;
}
__device__ __forceinline__ float lo32(u64 v) { return __uint_as_float((unsigned)(v & 0xffffffffu)); }
__device__ __forceinline__ float hi32(u64 v) { return __uint_as_float((unsigned)(v >> 32)); }
__device__ __forceinline__ u64 pack2(float x, float y) {
    return ((u64)__float_as_uint(y) << 32) | (u64)__float_as_uint(x);
}
__device__ __forceinline__ unsigned ld_acq(unsigned* p) {
    unsigned v;
    asm volatile("ld.acquire.gpu.u32 %0, [%1];" : "=r"(v) : "l"(p) : "memory");
    return v;
}
__device__ __forceinline__ void st_rel(unsigned* p, unsigned v) {
    asm volatile("st.release.gpu.u32 [%0], %1;" :: "l"(p), "r"(v) : "memory");
}

// ---------------- kernel 1: pre-projection GEMM ----------------
__global__ void __launch_bounds__(256) pre_gemm(const float* __restrict__ x,
                                                const float* __restrict__ W_ih,
                                                const float* __restrict__ b_ih,
                                                const float* __restrict__ b_hh) {
    __shared__ float Xs[64 * 65];
    __shared__ float Ws[64 * 65];
    const int t = blockIdx.y, jt = blockIdx.x;
    const int tid = threadIdx.x;
    const int ty = tid >> 4, tx = tid & 15;
    float acc[4][4] = {};
    for (int kc = 0; kc < 4; ++kc) {
        __syncthreads();
        for (int i = tid; i < 4096; i += 256) {
            int r = i >> 6, kk = i & 63;
            Xs[r * 65 + kk] = x[(t * 64 + r) * 256 + kc * 64 + kk];
            Ws[r * 65 + kk] = W_ih[(jt * 64 + r) * 257 + 1 + kc * 64 + kk];
        }
        __syncthreads();
        #pragma unroll 8
        for (int kk = 0; kk < 64; ++kk) {
            float wv[4], xv[4];
            #pragma unroll
            for (int a = 0; a < 4; ++a) wv[a] = Ws[(ty * 4 + a) * 65 + kk];
            #pragma unroll
            for (int c = 0; c < 4; ++c) xv[c] = Xs[(tx * 4 + c) * 65 + kk];
            #pragma unroll
            for (int a = 0; a < 4; ++a)
                #pragma unroll
                for (int c = 0; c < 4; ++c)
                    acc[a][c] = fmaf(wv[a], xv[c], acc[a][c]);
        }
    }
    #pragma unroll
    for (int a = 0; a < 4; ++a) {
        int j = jt * 64 + ty * 4 + a;
        float bias = b_ih[j] + b_hh[j];
        #pragma unroll
        for (int c = 0; c < 4; ++c) {
            int b = tx * 4 + c;
            g_preT[(t * 512 + j) * 64 + b] = acc[a][c] + bias;
        }
    }
}

// ---------------- init: s -> buf0 [k][b]; reset all 128 flags ----------------
__global__ void init_h(const float* __restrict__ s) {
    if (threadIdx.x < 2) g_flag[(blockIdx.x * 2 + threadIdx.x) * 32] = 0u;
    int b = blockIdx.x;
    int j = threadIdx.x;
    g_hbuf[j * 64 + b] = s[b * 512 + j];
}

// ---------------- kernel 2: half-pipelines with LOCAL timestep boundary ----------------
// Each block accumulates the FULL acc_s for its (k,b) load-slice in registers.
// On all-halt, the next timestep's n=0 GEMM runs immediately from registers:
// no rendezvous, no h reload. Rendezvous per timestep: q_f+1 (was q_f+2).
__global__ void __launch_bounds__(256, 1) rnn_act(const float* __restrict__ W_hh,
                                                  const float* __restrict__ W_ih,
                                                  const float* __restrict__ W_halt,
                                                  const float* __restrict__ b_halt,
                                                  float* __restrict__ pond_out) {
    __shared__ __align__(16) u64   sh_W2[4096];    // [k=512][j=8] dup-pairs (32 KB)
    __shared__ __align__(16) u64   sh_part[1024];  // [grp=8][j=8][pair=16]     (8 KB)
    __shared__ __align__(16) float sh_hp[256];     // haltv partials [warp=8][b=32]
    __shared__ float sh_whalt[8];
    __shared__ float sh_wih0[8];
    __shared__ float sh_bhalt;

    const int blk  = blockIdx.x;
    const int jg   = blk >> 1, half = blk & 1;
    const int tid  = threadIdx.x;
    const int warp = tid >> 5, lane = tid & 31;
    const int r4 = lane >> 3, q = lane & 7;        // GEMM lane map
    const int jo = (warp << 1) + (lane >> 4);      // output map (warps 0-3)
    const int po = lane & 15;                      // decision pair 0..15
    const int b0 = (half << 5) + (po << 1);
    const int gjrow = jg * 8 + jo;

    for (int i = tid; i < 4096; i += 256) {
        int jj = i >> 9, k = i & 511;
        unsigned wb = __float_as_uint(W_hh[(jg * 8 + jj) * 512 + k]);
        sh_W2[k * 8 + jj] = ((u64)wb << 32) | (u64)wb;
    }
    if (tid < 8) {
        sh_whalt[tid] = W_halt[jg * 8 + tid];
        sh_wih0[tid]  = W_ih[(jg * 8 + tid) * 257];
    }
    if (tid == 0) sh_bhalt = b_halt[0];
    __syncthreads();

    unsigned m = 0;
    int m3 = 0, nx3 = 1;
    int t = 0, n = 0;                              // uniform within half
    u64 accs[32];                                  // acc_s for this lane's (k,b) slice
    #pragma unroll
    for (int i = 0; i < 32; ++i) accs[i] = 0ull;
    float cumx = 0.f, cumy = 0.f;                  // replicated halt state (pair po)
    int   hlx = 0, hly = 0;
    float pondx = 0.f, pondy = 0.f;

    unsigned* myflag = &g_flag[((half << 6) + (warp << 3) + (lane < 8 ? lane : 0)) << 5];

    for (;;) {
        // ---- wait + load h(n-1) and haltv(n-1) ----
        for (;;) {
            unsigned v = (lane < 8) ? ld_acq(myflag) : 0xffffffffu;
            if (__all_sync(0xffffffffu, v >= m)) break;
            __nanosleep(32);
        }
        ulonglong2 h4[16];
        {
            const ulonglong2* bufv = (const ulonglong2*)((const u64*)g_hbuf + m3 * 16384);
            #pragma unroll
            for (int c = 0; c < 16; ++c)
                h4[c] = __ldcg(bufv + ((warp << 6) + (c << 2) + r4) * 16 + (half << 3) + q);
        }
        int allh = 0;
        if (n >= 1) {
            // haltv consumer
            float2 hp2 = make_float2(0.f, 0.f);
            {
                const float2* hvr = (const float2*)(g_haltv + (m3 * 2 + half) * 8192);
                const int rbase = (warp << 5) + (lane >> 4);
                const int fi = lane & 15;
                #pragma unroll
                for (int i = 0; i < 16; ++i) {
                    float2 v = __ldcg(hvr + (rbase + (i << 1)) * 16 + fi);
                    hp2.x += v.x; hp2.y += v.y;
                }
                hp2.x += __shfl_xor_sync(0xffffffffu, hp2.x, 16);
                hp2.y += __shfl_xor_sync(0xffffffffu, hp2.y, 16);
            }
            if (lane < 16) *(float2*)(sh_hp + (warp << 5) + (lane << 1)) = hp2;
            __syncthreads();                                           // S1
            // replicated halt decision for ponder q = n-1
            float sx = 0.f, sy = 0.f;
            #pragma unroll
            for (int w8 = 0; w8 < 8; ++w8) {
                float2 v = *(const float2*)(sh_hp + (w8 << 5) + (po << 1));
                sx += v.x; sy += v.y;
            }
            float px = 1.f / (1.f + expf(-(sx + sh_bhalt)));
            float py = 1.f / (1.f + expf(-(sy + sh_bhalt)));
            if (hlx) px = 0.f;
            if (hly) py = 0.f;
            int ihx = (!hlx) && (((cumx + px) >= 0.99f) || (n - 1 == NMAX - 1));
            int ihy = (!hly) && (((cumy + py) >= 0.99f) || (n - 1 == NMAX - 1));
            float wx = ihx ? (1.f - cumx) : px;
            float wy = ihy ? (1.f - cumy) : py;
            if (ihx) pondx = (1.f - cumx) + (float)n;
            if (ihy) pondy = (1.f - cumy) + (float)n;
            cumx += px; cumy += py;
            hlx |= ihx; hly |= ihy;
            allh = __all_sync(0xffffffffu, hlx && hly);
            // acc_s update: shuffle per-b weights into GEMM lane layout
            float w0x = __shfl_sync(0xffffffffu, wx, (q << 1));
            float w0y = __shfl_sync(0xffffffffu, wy, (q << 1));
            float w1x = __shfl_sync(0xffffffffu, wx, (q << 1) + 1);
            float w1y = __shfl_sync(0xffffffffu, wy, (q << 1) + 1);
            u64 wp0 = pack2(w0x, w0y), wp1 = pack2(w1x, w1y);
            #pragma unroll
            for (int c = 0; c < 16; ++c) {
                ffma2(accs[2 * c],     h4[c].x, wp0);
                ffma2(accs[2 * c + 1], h4[c].y, wp1);
            }
        }
        int add_flag = (n == 0);
        if (allh) {
            // ---- finalize timestep t locally ----
            if (jg == 0) {
                // block jg=0 holds the full half-slice of acc_s; write accsT
                #pragma unroll
                for (int c = 0; c < 16; ++c) {
                    int k = (warp << 6) + (c << 2) + r4;
                    *(ulonglong2*)(g_accsT + ((t * 512 + k) << 6) + (half << 5) + (q << 2)) =
                        make_ulonglong2(accs[2 * c], accs[2 * c + 1]);
                }
                if (warp == 0 && lane < 16)
                    *(float2*)(pond_out + t * 64 + (half << 5) + (po << 1)) =
                        make_float2(pondx, pondy);
            }
            cumx = cumy = 0.f; hlx = hly = 0; pondx = pondy = 0.f;
            // next timestep's h-input = acc_s (register-resident); reset acc
            #pragma unroll
            for (int c = 0; c < 16; ++c) {
                h4[c] = make_ulonglong2(accs[2 * c], accs[2 * c + 1]);
                accs[2 * c] = 0ull; accs[2 * c + 1] = 0ull;
            }
            ++t; n = 0; add_flag = 1;
            if (t == S_LEN) break;                 // uniform across the half
        }
        // ---- GEMM on h4 (loaded h, or register acc at the local boundary) ----
        u64 gac[8][2] = {};
        #pragma unroll
        for (int c = 0; c < 16; ++c) {
            const int k = (warp << 6) + (c << 2) + r4;
            ulonglong2 h2v = h4[c];
            const ulonglong2* wr = (const ulonglong2*)(sh_W2 + (k << 3));
            ulonglong2 w01 = wr[0], w23 = wr[1], w45 = wr[2], w67 = wr[3];
            ffma2(gac[0][0], h2v.x, w01.x); ffma2(gac[0][1], h2v.y, w01.x);
            ffma2(gac[1][0], h2v.x, w01.y); ffma2(gac[1][1], h2v.y, w01.y);
            ffma2(gac[2][0], h2v.x, w23.x); ffma2(gac[2][1], h2v.y, w23.x);
            ffma2(gac[3][0], h2v.x, w23.y); ffma2(gac[3][1], h2v.y, w23.y);
            ffma2(gac[4][0], h2v.x, w45.x); ffma2(gac[4][1], h2v.y, w45.x);
            ffma2(gac[5][0], h2v.x, w45.y); ffma2(gac[5][1], h2v.y, w45.y);
            ffma2(gac[6][0], h2v.x, w67.x); ffma2(gac[6][1], h2v.y, w67.x);
            ffma2(gac[7][0], h2v.x, w67.y); ffma2(gac[7][1], h2v.y, w67.y);
        }
        #pragma unroll
        for (int jj = 0; jj < 8; ++jj) {
            #pragma unroll
            for (int pp = 0; pp < 2; ++pp) {
                u64 v = gac[jj][pp];
                v = add2(v, __shfl_xor_sync(0xffffffffu, v, 8));
                v = add2(v, __shfl_xor_sync(0xffffffffu, v, 16));
                gac[jj][pp] = v;
            }
        }
        if (lane < 8) {
            ulonglong2* pp = (ulonglong2*)(sh_part + (warp << 7));
            #pragma unroll
            for (int jj = 0; jj < 8; ++jj)
                pp[(jj << 3) + q] = make_ulonglong2(gac[jj][0], gac[jj][1]);
        }
        // prefetch pre-projection for the (possibly advanced) t
        float2 pre2 = make_float2(0.f, 0.f);
        if (warp < 4)
            pre2 = __ldg((const float2*)(g_preT + ((t * 512 + gjrow) << 6) + b0));
        __syncthreads();                                               // S2
        if (warp < 4) {
            float sx = 0.f, sy = 0.f;
            #pragma unroll
            for (int g = 0; g < 8; ++g) {
                u64 v = sh_part[(g << 7) + (jo << 4) + po];
                sx += lo32(v); sy += hi32(v);
            }
            float ax = sx + pre2.x, ay = sy + pre2.y;
            if (add_flag) { float f = sh_wih0[jo]; ax += f; ay += f; }
            float hx = tanhf(ax), hyv = tanhf(ay);
            *((u64*)g_hbuf + nx3 * 16384 + gjrow * 32 + (half << 4) + po) = pack2(hx, hyv);
            float2 hw = make_float2(sh_whalt[jo] * hx, sh_whalt[jo] * hyv);
            hw.x += __shfl_xor_sync(0xffffffffu, hw.x, 16);
            hw.y += __shfl_xor_sync(0xffffffffu, hw.y, 16);
            if (lane < 16) {
                float2* hvw = (float2*)(g_haltv + (nx3 * 2 + half) * 8192);
                hvw[((jg << 2) + warp) * 16 + po] = hw;
            }
            asm volatile("bar.sync 1, 128;" ::: "memory");     // warps 0-3 only
            if (tid == 0) st_rel(&g_flag[((half << 6) + jg) << 5], m + 1);
        }
        ++n;
        ++m;
        m3 = nx3; nx3 = (nx3 + 1 == 3) ? 0 : nx3 + 1;
    }
}

// ---------------- kernel 3: output GEMM ----------------
__global__ void __launch_bounds__(256) out_gemm(const float* __restrict__ W_out,
                                                const float* __restrict__ b_out,
                                                float* __restrict__ out) {
    __shared__ float As[64 * 65];
    __shared__ float Ws[64 * 65];
    const int t = blockIdx.y, ot = blockIdx.x;
    const int tid = threadIdx.x;
    const int ty = tid >> 4, tx = tid & 15;
    float acc[4][4] = {};
    for (int kc = 0; kc < 8; ++kc) {
        __syncthreads();
        for (int i = tid; i < 4096; i += 256) {
            int r = i >> 6, c = i & 63;
            As[r * 65 + c] = g_accsT[(t * 512 + kc * 64 + r) * 64 + c];
            Ws[r * 65 + c] = W_out[(ot * 64 + r) * 512 + kc * 64 + c];
        }
        __syncthreads();
        #pragma unroll 8
        for (int kk = 0; kk < 64; ++kk) {
            float wv[4], xv[4];
            #pragma unroll
            for (int a = 0; a < 4; ++a) wv[a] = Ws[(ty * 4 + a) * 65 + kk];
            #pragma unroll
            for (int c = 0; c < 4; ++c) xv[c] = As[kk * 65 + tx * 4 + c];
            #pragma unroll
            for (int a = 0; a < 4; ++a)
                #pragma unroll
                for (int c = 0; c < 4; ++c)
                    acc[a][c] = fmaf(wv[a], xv[c], acc[a][c]);
        }
    }
    #pragma unroll
    for (int a = 0; a < 4; ++a) {
        int o = ot * 64 + ty * 4 + a;
        float bias = b_out[o];
        #pragma unroll
        for (int c = 0; c < 4; ++c) {
            int b = tx * 4 + c;
            out[(t * 64 + b) * 256 + o] = acc[a][c] + bias;
        }
    }
}

extern "C" void kernel_launch(void* const* d_in, const int* in_sizes, int n_in,
                              void* d_out, int out_size) {
    const float* x      = (const float*)d_in[0];
    const float* s      = (const float*)d_in[1];
    const float* W_ih   = (const float*)d_in[2];
    const float* b_ih   = (const float*)d_in[3];
    const float* W_hh   = (const float*)d_in[4];
    const float* b_hh   = (const float*)d_in[5];
    const float* W_out  = (const float*)d_in[6];
    const float* b_out  = (const float*)d_in[7];
    const float* W_halt = (const float*)d_in[8];
    const float* b_halt = (const float*)d_in[9];
    float* out  = (float*)d_out;                       // outputs [S,B,O]
    float* pond = out + S_LEN * B_SZ * O_SZ;           // ponder  [S,B]

    dim3 preg(8, S_LEN);
    pre_gemm<<<preg, 256>>>(x, W_ih, b_ih, b_hh);
    init_h<<<B_SZ, H_SZ>>>(s);
    rnn_act<<<NBLK, 256>>>(W_hh, W_ih, W_halt, b_halt, pond);
    dim3 outg(4, S_LEN);
    out_gemm<<<outg, 256>>>(W_out, b_out, out);
}